// round 8
// baseline (speedup 1.0000x reference)
#include <cuda_runtime.h>
#include <cuda_bf16.h>
#include <math.h>
#include <stdint.h>

// ===========================================================================
// FCOS head via mma.sync bf16 tensor cores (compute_100-safe; no tcgen05).
// Conv3x3 as implicit GEMM, bf16 hi/lo 3-term split (AhBh+AhBl+AlBh) ~1e-6.
// R8: same as R7 (.cs streaming convout, GN stats fused into conv epilogue,
// launch order tuned for ncu) + vectorized gn_apply (uint4 stores).
// ===========================================================================

#define BATCH 8
#define KDIM 2304
#define MAXPADPOS ((size_t)BATCH * 102 * 154)
#define MAXPOS    ((size_t)BATCH * 100 * 152)
#define PSMAX 950

// ---------------- device buffers -------------------------------------------
__device__ __align__(16) __nv_bfloat16 g_Xin_h[MAXPADPOS * 256];
__device__ __align__(16) __nv_bfloat16 g_Xin_l[MAXPADPOS * 256];
__device__ __align__(16) __nv_bfloat16 g_Xa_h [MAXPADPOS * 256];
__device__ __align__(16) __nv_bfloat16 g_Xa_l [MAXPADPOS * 256];
__device__ __align__(16) __nv_bfloat16 g_Xb_h [MAXPADPOS * 256];
__device__ __align__(16) __nv_bfloat16 g_Xb_l [MAXPADPOS * 256];
__device__ __align__(16) float g_convout[MAXPOS * 256];
__device__ __align__(16) __nv_bfloat16 g_Wth[8 * 256 * KDIM];
__device__ __align__(16) __nv_bfloat16 g_Wtl[8 * 256 * KDIM];
__device__ __align__(16) __nv_bfloat16 g_Whh[2 * 128 * KDIM];
__device__ __align__(16) __nv_bfloat16 g_Whl[2 * 128 * KDIM];
__device__ float g_hb[2 * 128];
__device__ float g_psA [256 * PSMAX];
__device__ float g_ps2A[256 * PSMAX];
__device__ float g_mean[256];
__device__ float g_rstd[256];

__device__ __forceinline__ void bf_split(float v, __nv_bfloat16& h, __nv_bfloat16& l) {
    h = __float2bfloat16(v);
    l = __float2bfloat16(v - __bfloat162float(h));
}

// ---------------- PTX helpers ----------------------------------------------
__device__ __forceinline__ uint32_t smem_to_u32(const void* p) {
    uint32_t a;
    asm("{ .reg .u64 t; cvta.to.shared.u64 t, %1; cvt.u32.u64 %0, t; }"
        : "=r"(a) : "l"(p));
    return a;
}
#define CP_ASYNC16(dst, src) \
    asm volatile("cp.async.cg.shared.global [%0], [%1], 16;" \
                 :: "r"(dst), "l"(src))
#define CP_COMMIT() asm volatile("cp.async.commit_group;" ::: "memory")
#define CP_WAIT(n)  asm volatile("cp.async.wait_group %0;" :: "n"(n) : "memory")

__device__ __forceinline__ void ldsm4(uint32_t (&r)[4], uint32_t a) {
    asm volatile("ldmatrix.sync.aligned.m8n8.x4.shared.b16 {%0,%1,%2,%3}, [%4];"
        : "=r"(r[0]), "=r"(r[1]), "=r"(r[2]), "=r"(r[3]) : "r"(a));
}
__device__ __forceinline__ void mma16816(float* d, const uint32_t* a, const uint32_t* b) {
    asm volatile(
        "mma.sync.aligned.m16n8k16.row.col.f32.bf16.bf16.f32 "
        "{%0,%1,%2,%3}, {%4,%5,%6,%7}, {%8,%9}, {%0,%1,%2,%3};"
        : "+f"(d[0]), "+f"(d[1]), "+f"(d[2]), "+f"(d[3])
        : "r"(a[0]), "r"(a[1]), "r"(a[2]), "r"(a[3]), "r"(b[0]), "r"(b[1]));
}

// ---------------- prep kernels ---------------------------------------------
__global__ void prep_weights_kernel(const float* __restrict__ cls_w,
                                    const float* __restrict__ box_w)
{
    long idx = (long)blockIdx.x * blockDim.x + threadIdx.x;
    if (idx >= 8L * 256 * KDIM) return;
    int j = (int)(idx / (256 * KDIM));
    int rem = (int)(idx - (long)j * 256 * KDIM);
    int m = rem / KDIM, k = rem - m * KDIM;
    int tap = k >> 8, ci = k & 255;
    const float* src = (j < 4) ? cls_w + (long)j * 256 * KDIM
                               : box_w + (long)(j - 4) * 256 * KDIM;
    float v = src[(m * 256 + ci) * 9 + tap];
    bf_split(v, g_Wth[idx], g_Wtl[idx]);
}

__global__ void prep_heads_kernel(const float* __restrict__ logits_w,
                                  const float* __restrict__ logits_b,
                                  const float* __restrict__ ctr_w,
                                  const float* __restrict__ ctr_b,
                                  const float* __restrict__ reg_w,
                                  const float* __restrict__ reg_b)
{
    long idx = (long)blockIdx.x * blockDim.x + threadIdx.x;
    if (idx >= 2L * 128 * KDIM) return;
    int which = (int)(idx / (128 * KDIM));
    int rem = (int)(idx - (long)which * 128 * KDIM);
    int m = rem / KDIM, k = rem - m * KDIM;
    int tap = k >> 8, ci = k & 255;
    float v = 0.f;
    if (which == 0) {
        if (m < 80)       v = logits_w[(m * 256 + ci) * 9 + tap];
        else if (m == 80) v = ctr_w[ci * 9 + tap];
    } else {
        if (m < 4) v = reg_w[(m * 256 + ci) * 9 + tap];
    }
    bf_split(v, g_Whh[idx], g_Whl[idx]);
    if (k == 0) {
        float bv = 0.f;
        if (which == 0) { if (m < 80) bv = logits_b[m]; else if (m == 80) bv = ctr_b[0]; }
        else            { if (m < 4)  bv = reg_b[m]; }
        g_hb[which * 128 + m] = bv;
    }
}

// Interior: NCHW f32 feat -> padded NHWC bf16 hi/lo (Xin). Tail: zero borders
// of all three buffer pairs.
__global__ void prep_act_kernel(const float* __restrict__ feat, int H, int W)
{
    const int HW = H * W;
    const int Hp = H + 2, Wp = W + 2;
    const long nInt = (long)BATCH * HW * 256;
    const int cnt = 2 * Wp + 2 * H;
    const long nBor = (long)BATCH * cnt * 32;
    long idx = (long)blockIdx.x * blockDim.x + threadIdx.x;
    if (idx < nInt) {
        int c = (int)(idx & 255);
        int p = (int)(idx >> 8);
        int b = p / HW, hw = p - b * HW;
        int y = hw / W, x = hw - y * W;
        float v = feat[((long)(b * 256 + c) * H + y) * W + x];
        long a = (((long)b * Hp + y + 1) * Wp + x + 1) * 256 + c;
        bf_split(v, g_Xin_h[a], g_Xin_l[a]);
        return;
    }
    idx -= nInt;
    if (idx >= 3 * nBor) return;
    int pair = (int)(idx / nBor);
    long r0 = idx - (long)pair * nBor;
    int b = (int)(r0 / (cnt * 32));
    int r = (int)(r0 - (long)b * cnt * 32);
    int i = r >> 5, q = r & 31;
    int y, x;
    if (i < Wp)              { y = 0;      x = i; }
    else if (i < 2 * Wp)     { y = Hp - 1; x = i - Wp; }
    else if (i < 2 * Wp + H) { y = 1 + (i - 2 * Wp);     x = 0; }
    else                     { y = 1 + (i - 2 * Wp - H); x = Wp - 1; }
    long a = (((long)b * Hp + y) * Wp + x) * 256 + q * 8;
    uint4 z = make_uint4(0, 0, 0, 0);
    __nv_bfloat16* bh = (pair == 0) ? g_Xin_h : (pair == 1) ? g_Xa_h : g_Xb_h;
    __nv_bfloat16* bl = (pair == 0) ? g_Xin_l : (pair == 1) ? g_Xa_l : g_Xb_l;
    *(uint4*)(bh + a) = z;
    *(uint4*)(bl + a) = z;
}

// ---------------- conv via mma.sync ----------------------------------------
#define ROWB 80
#define TILE_BYTES (128 * ROWB)          // 10240
#define STAGE_BYTES (4 * TILE_BYTES)     // 40960
#define DYN_SMEM (2 * STAGE_BYTES + 512 + 64)

__global__ __launch_bounds__(256, 2) void conv_mma_kernel(
    const __nv_bfloat16* __restrict__ Wh, const __nv_bfloat16* __restrict__ Wl,
    const float* __restrict__ bias,
    const __nv_bfloat16* __restrict__ Xh, const __nv_bfloat16* __restrict__ Xl,
    float* __restrict__ convout, float* __restrict__ dout,
    const float* __restrict__ scales, int lvl,
    int H, int W, int mode, long out_boff, long lvl_off)
{
    const int Hp = H + 2, Wp = W + 2, HW = H * W;
    const int N = BATCH * HW;
    const int n0 = blockIdx.x * 128;
    const int m0 = blockIdx.y * 128;
    const int tid = threadIdx.x, wid = tid >> 5, lid = tid & 31;

    extern __shared__ char dsm[];
    const uint32_t sb0 = smem_to_u32(dsm);
    int* sbase = (int*)(dsm + 2 * STAGE_BYTES);

    if (tid < 128) {
        int p = n0 + tid;
        if (p >= N) p = N - 1;
        int b = p / HW, hw = p - b * HW;
        int y = hw / W, x = hw - y * W;
        sbase[tid] = ((b * Hp + y) * Wp + x) * 256;
    }
    __syncthreads();

    // Per-thread load channels: 8 cp.async (16B each) per stage.
    const __nv_bfloat16* gbase[8];
    uint32_t sdst[8];
    bool isA[8];
#pragma unroll
    for (int c = 0; c < 8; c++) {
        int id = c * 256 + tid;        // 0..2047
        int tile = id >> 9;            // 0:Ah 1:Al 2:Bh 3:Bl
        int e = id & 511;
        int row = e >> 2, c4 = e & 3;
        isA[c] = (tile < 2);
        if (tile == 0)      gbase[c] = Wh + (long)(m0 + row) * KDIM + c4 * 8;
        else if (tile == 1) gbase[c] = Wl + (long)(m0 + row) * KDIM + c4 * 8;
        else if (tile == 2) gbase[c] = Xh + (long)sbase[row] + c4 * 8;
        else                gbase[c] = Xl + (long)sbase[row] + c4 * 8;
        sdst[c] = sb0 + tile * TILE_BYTES + row * ROWB + c4 * 16;
    }

    const int NSTAGE = KDIM / 32;      // 72
    const int wm = wid & 3, wn = wid >> 2;

    float acc[2][8][4];
#pragma unroll
    for (int i = 0; i < 2; i++)
#pragma unroll
        for (int j = 0; j < 8; j++)
#pragma unroll
            for (int k = 0; k < 4; k++) acc[i][j][k] = 0.f;

    auto issue = [&](int s) {
        const uint32_t boff = (uint32_t)(s & 1) * STAGE_BYTES;
        const int kA = s * 32;
        const int tap = s >> 3;
        const int kB = ((tap / 3) * Wp + (tap % 3)) * 256 + (s & 7) * 32;
#pragma unroll
        for (int c = 0; c < 8; c++)
            CP_ASYNC16(sdst[c] + boff, gbase[c] + (isA[c] ? kA : kB));
        CP_COMMIT();
    };

    issue(0);
    for (int s = 0; s < NSTAGE; s++) {
        if (s + 1 < NSTAGE) { issue(s + 1); CP_WAIT(1); }
        else                { CP_WAIT(0); }
        __syncthreads();

        const uint32_t tb = sb0 + (uint32_t)(s & 1) * STAGE_BYTES;
        const uint32_t Ahb = tb, Alb = tb + TILE_BYTES;
        const uint32_t Bhb = tb + 2 * TILE_BYTES, Blb = tb + 3 * TILE_BYTES;

#pragma unroll
        for (int sl = 0; sl < 2; sl++) {
            uint32_t ah[2][4], al[2][4];
#pragma unroll
            for (int mi = 0; mi < 2; mi++) {
                uint32_t ao = (uint32_t)((wm * 32 + mi * 16 + (lid & 15)) * ROWB
                                         + (sl * 16 + (lid >> 4) * 8) * 2);
                ldsm4(ah[mi], Ahb + ao);
                ldsm4(al[mi], Alb + ao);
            }
#pragma unroll
            for (int ng = 0; ng < 4; ng++) {
                const int q = lid >> 3;
                uint32_t bo = (uint32_t)((wn * 64 + ng * 16 + (q >> 1) * 8 + (lid & 7)) * ROWB
                                         + (sl * 16 + (q & 1) * 8) * 2);
                uint32_t bh[4], bl[4];
                ldsm4(bh, Bhb + bo);
                ldsm4(bl, Blb + bo);
#pragma unroll
                for (int mi = 0; mi < 2; mi++) {
#pragma unroll
                    for (int h = 0; h < 2; h++) {
                        float* d = acc[mi][ng * 2 + h];
                        mma16816(d, ah[mi], &bh[h * 2]);
                        mma16816(d, ah[mi], &bl[h * 2]);
                        mma16816(d, al[mi], &bh[h * 2]);
                    }
                }
            }
        }
        __syncthreads();
    }

    // ---------------- epilogue ----------------
    const float sc = (mode == 2) ? scales[lvl] : 0.f;
    const int b0 = n0 / HW;
    float* sred = (float*)dsm;           // 96 floats: s[48], s2[48]
    float ts[12], ts2[12];
    if (mode == 0) {
        if (tid < 96) sred[tid] = 0.f;
#pragma unroll
        for (int i = 0; i < 12; i++) { ts[i] = 0.f; ts2[i] = 0.f; }
        __syncthreads();
    }

#pragma unroll
    for (int mi = 0; mi < 2; mi++) {
        const int mlo = m0 + wm * 32 + mi * 16 + (lid >> 2);
        const float bv0 = bias[mlo];
        const float bv1 = bias[mlo + 8];
#pragma unroll
        for (int ng = 0; ng < 4; ng++) {
#pragma unroll
            for (int h = 0; h < 2; h++) {
                const float* d = acc[mi][ng * 2 + h];
                const int n = n0 + wn * 64 + ng * 16 + h * 8 + 2 * (lid & 3);
#pragma unroll
                for (int e = 0; e < 4; e++) {
                    const int p = n + (e & 1);
                    const int half = (e >> 1);
                    const int m = mlo + half * 8;
                    if (p >= N) continue;
                    float v = d[e] + (half ? bv1 : bv0);
                    if (mode == 0) {
                        __stcs(&convout[(size_t)p * 256 + m], v);
                        int db = p / HW - b0;
                        int si = (mi * 2 + half) * 3 + db;
                        ts[si] += v; ts2[si] += v * v;
                    } else {
                        int b = p / HW, hw = p - b * HW;
                        long ob = (long)b * out_boff + lvl_off;
                        if (mode == 1) {
                            if (m < 80)       __stcs(&dout[ob + (long)m * HW + hw], v);
                            else if (m == 80) __stcs(&dout[ob + 84L * HW + hw], v);
                        } else {
                            if (m < 4) __stcs(&dout[ob + (long)(80 + m) * HW + hw],
                                              expf(sc * v));
                        }
                    }
                }
            }
        }
    }

    if (mode == 0) {
#pragma unroll
        for (int i = 0; i < 12; i++) {
            if (ts[i] == 0.f && ts2[i] == 0.f) continue;
            int db = i % 3, q = i / 3;
            int half = q & 1, mi = q >> 1;
            int gl = wm * 4 + mi * 2 + half;
            atomicAdd(&sred[db * 16 + gl], ts[i]);
            atomicAdd(&sred[48 + db * 16 + gl], ts2[i]);
        }
        __syncthreads();
        if (tid < 48) {
            int db = tid >> 4, gl = tid & 15;
            int b = b0 + db;
            if (b < BATCH) {
                int g = (m0 >> 3) + gl;
                g_psA [((b * 32) + g) * PSMAX + blockIdx.x] = sred[tid];
                g_ps2A[((b * 32) + g) * PSMAX + blockIdx.x] = sred[48 + tid];
            }
        }
    }
}

// ---------------- GroupNorm stage 2 + apply ---------------------------------
__global__ __launch_bounds__(256) void gn_stats2_kernel(int HW, int nblk)
{
    const int bg = blockIdx.x;
    const int b = bg >> 5;
    const int N = BATCH * HW;
    float s = 0.f, s2 = 0.f;
    for (int nb = threadIdx.x; nb < nblk; nb += 256) {
        int p0 = nb * 128;
        int bfirst = p0 / HW;
        int pl = p0 + 127; if (pl >= N) pl = N - 1;
        int blast = pl / HW;
        if (b >= bfirst && b <= blast) {
            s  += g_psA [bg * PSMAX + nb];
            s2 += g_ps2A[bg * PSMAX + nb];
        }
    }
    __shared__ float ss[256], ss2[256];
    ss[threadIdx.x] = s; ss2[threadIdx.x] = s2;
    __syncthreads();
    for (int o = 128; o > 0; o >>= 1) {
        if (threadIdx.x < o) {
            ss[threadIdx.x]  += ss[threadIdx.x + o];
            ss2[threadIdx.x] += ss2[threadIdx.x + o];
        }
        __syncthreads();
    }
    if (threadIdx.x == 0) {
        float cnt = 8.f * HW;
        float mean = ss[0] / cnt;
        float var  = ss2[0] / cnt - mean * mean;
        g_mean[bg] = mean;
        g_rstd[bg] = rsqrtf(var + 1e-5f);
    }
}

// Vectorized GN apply + ReLU: one thread per (position, group) = 8 channels,
// float4 streaming loads, uint4 (8 x bf16) stores.
__global__ __launch_bounds__(256) void gn_apply_kernel(
    const float* __restrict__ co,
    __nv_bfloat16* __restrict__ xh, __nv_bfloat16* __restrict__ xl,
    const float* __restrict__ gamma, const float* __restrict__ beta,
    int H, int W)
{
    const int HW = H * W;
    long idx = (long)blockIdx.x * blockDim.x + threadIdx.x;
    if (idx >= (long)BATCH * HW * 32) return;
    int g = (int)(idx & 31);
    int p = (int)(idx >> 5);
    int b = p / HW, hw = p - b * HW;
    int y = hw / W, x = hw - y * W;
    const int bg = b * 32 + g;
    const float mean = g_mean[bg], rstd = g_rstd[bg];
    const float* src = co + (size_t)p * 256 + g * 8;
    float4 v0 = __ldcs((const float4*)src);
    float4 v1 = __ldcs((const float4*)(src + 4));
    float vv[8] = {v0.x, v0.y, v0.z, v0.w, v1.x, v1.y, v1.z, v1.w};
    __nv_bfloat16 hh[8], ll[8];
#pragma unroll
    for (int i = 0; i < 8; i++) {
        int c = g * 8 + i;
        float v = (vv[i] - mean) * rstd * gamma[c] + beta[c];
        v = v > 0.f ? v : 0.f;
        bf_split(v, hh[i], ll[i]);
    }
    long a = (((long)b * (H + 2) + y + 1) * (W + 2) + x + 1) * 256 + g * 8;
    *(uint4*)(xh + a) = *(const uint4*)hh;
    *(uint4*)(xl + a) = *(const uint4*)ll;
}

// All-level FCOS locations in one launch.
__global__ __launch_bounds__(256) void loc_all_kernel(float* __restrict__ out, long base)
{
    static const int WS[5]  = {152, 76, 38, 19, 10};
    static const int STR[5] = {8, 16, 32, 64, 128};
    static const int OFF[5] = {0, 15200, 19000, 19950, 20197};
    int idx = blockIdx.x * blockDim.x + threadIdx.x;
    if (idx >= 20267) return;
    int l = 4;
    if (idx < 15200) l = 0;
    else if (idx < 19000) l = 1;
    else if (idx < 19950) l = 2;
    else if (idx < 20197) l = 3;
    int r = idx - OFF[l];
    int y = r / WS[l], x = r - y * WS[l];
    out[base + 2 * idx]     = (float)(x * STR[l] + STR[l] / 2);
    out[base + 2 * idx + 1] = (float)(y * STR[l] + STR[l] / 2);
}

// ---------------------------------------------------------------------------
extern "C" void kernel_launch(void* const* d_in, const int* in_sizes, int n_in,
                              void* d_out, int out_size)
{
    (void)in_sizes; (void)n_in; (void)out_size;
    const float* feats[5];
    for (int i = 0; i < 5; i++) feats[i] = (const float*)d_in[i];
    const float* cls_w    = (const float*)d_in[5];
    const float* cls_b    = (const float*)d_in[6];
    const float* cls_gn_g = (const float*)d_in[7];
    const float* cls_gn_b = (const float*)d_in[8];
    const float* box_w    = (const float*)d_in[9];
    const float* box_b    = (const float*)d_in[10];
    const float* box_gn_g = (const float*)d_in[11];
    const float* box_gn_b = (const float*)d_in[12];
    const float* logits_w = (const float*)d_in[13];
    const float* logits_b = (const float*)d_in[14];
    const float* ctr_w    = (const float*)d_in[15];
    const float* ctr_b    = (const float*)d_in[16];
    const float* reg_w    = (const float*)d_in[17];
    const float* reg_b    = (const float*)d_in[18];
    const float* scales   = (const float*)d_in[19];
    float* out = (float*)d_out;

    cudaFuncSetAttribute(conv_mma_kernel,
                         cudaFuncAttributeMaxDynamicSharedMemorySize, DYN_SMEM);

    __nv_bfloat16 *Xin_h, *Xin_l, *Xa_h, *Xa_l, *Xb_h, *Xb_l;
    __nv_bfloat16 *Wth, *Wtl, *Whh, *Whl;
    float *convout, *hb;
    cudaGetSymbolAddress((void**)&Xin_h, g_Xin_h);
    cudaGetSymbolAddress((void**)&Xin_l, g_Xin_l);
    cudaGetSymbolAddress((void**)&Xa_h, g_Xa_h);
    cudaGetSymbolAddress((void**)&Xa_l, g_Xa_l);
    cudaGetSymbolAddress((void**)&Xb_h, g_Xb_h);
    cudaGetSymbolAddress((void**)&Xb_l, g_Xb_l);
    cudaGetSymbolAddress((void**)&Wth, g_Wth);
    cudaGetSymbolAddress((void**)&Wtl, g_Wtl);
    cudaGetSymbolAddress((void**)&Whh, g_Whh);
    cudaGetSymbolAddress((void**)&Whl, g_Whl);
    cudaGetSymbolAddress((void**)&convout, g_convout);
    cudaGetSymbolAddress((void**)&hb, g_hb);

    static const int HS[5]  = {100, 50, 25, 13, 7};
    static const int WS[5]  = {152, 76, 38, 19, 10};

    long out_boff = 0;
    for (int l = 0; l < 5; l++) out_boff += 85L * HS[l] * WS[l];
    const long locs_base = (long)BATCH * out_boff;

    prep_weights_kernel<<<(int)((8L * 256 * KDIM + 255) / 256), 256>>>(cls_w, box_w);
    prep_heads_kernel<<<(int)((2L * 128 * KDIM + 255) / 256), 256>>>(
        logits_w, logits_b, ctr_w, ctr_b, reg_w, reg_b);

    long lvl_off = 0;
    for (int l = 0; l < 5; l++) {
        const int H = HS[l], W = WS[l], HW = H * W;
        const int N = BATCH * HW;
        const int nblk = (N + 127) / 128;
        const long tot = (long)N * 256;
        const int Hp = H + 2, Wp = W + 2;
        const int cnt = 2 * Wp + 2 * H;
        const long pa_tot = tot + 3L * BATCH * cnt * 32;
        const int pg = (int)((pa_tot + 255) / 256);
        const int ag = (int)(((long)N * 32 + 255) / 256);

        prep_act_kernel<<<pg, 256>>>(feats[l], H, W);

        __nv_bfloat16* srcs_h[4] = {Xin_h, Xa_h, Xb_h, Xa_h};
        __nv_bfloat16* srcs_l[4] = {Xin_l, Xa_l, Xb_l, Xa_l};
        __nv_bfloat16* dsts_h[4] = {Xa_h, Xb_h, Xa_h, Xb_h};
        __nv_bfloat16* dsts_l[4] = {Xa_l, Xb_l, Xa_l, Xb_l};

        dim3 gconv(nblk, 2);
        dim3 ghead(nblk, 1);

        for (int tower = 0; tower < 2; tower++) {
            const __nv_bfloat16* wtower_h = Wth + (long)tower * 4 * 256 * KDIM;
            const __nv_bfloat16* wtower_l = Wtl + (long)tower * 4 * 256 * KDIM;
            const float* btower = tower ? box_b : cls_b;
            const float* gg = tower ? box_gn_g : cls_gn_g;
            const float* gb = tower ? box_gn_b : cls_gn_b;
            for (int i = 0; i < 4; i++) {
                conv_mma_kernel<<<gconv, 256, DYN_SMEM>>>(
                    wtower_h + (long)i * 256 * KDIM, wtower_l + (long)i * 256 * KDIM,
                    btower + i * 256, srcs_h[i], srcs_l[i],
                    convout, nullptr, scales, l, H, W, 0, 0, 0);
                gn_stats2_kernel<<<256, 256>>>(HW, nblk);
                gn_apply_kernel<<<ag, 256>>>(convout, dsts_h[i], dsts_l[i],
                                             gg + i * 256, gb + i * 256, H, W);
            }
            if (tower == 0) {
                conv_mma_kernel<<<ghead, 256, DYN_SMEM>>>(
                    Whh, Whl, hb, Xb_h, Xb_l, nullptr, out, scales, l,
                    H, W, 1, out_boff, lvl_off);
            } else {
                conv_mma_kernel<<<ghead, 256, DYN_SMEM>>>(
                    Whh + (long)128 * KDIM, Whl + (long)128 * KDIM, hb + 128,
                    Xb_h, Xb_l, nullptr, out, scales, l,
                    H, W, 2, out_boff, lvl_off);
            }
        }
        lvl_off += 85L * HW;
    }
    loc_all_kernel<<<(20267 + 255) / 256, 256>>>(out, locs_base);
}

// round 10
// speedup vs baseline: 1.2255x; 1.2255x over previous
#include <cuda_runtime.h>
#include <cuda_fp16.h>
#include <math.h>
#include <stdint.h>

// ===========================================================================
// FCOS head via mma.sync fp16 tensor cores (compute_100-safe; no tcgen05).
// Conv3x3 as implicit GEMM. Weights split W = Wh + Wl (fp16 hi/lo, exact to
// ~2^-22); activations single fp16 -> 2 MMAs per k-step (was 3 with bf16).
// 3-slot cp.async ring, one __syncthreads per stage. GN stats fused into the
// conv epilogue (deterministic partials). Head convs skip dead M-rows.
// ===========================================================================

#define BATCH 8
#define KDIM 2304
#define MAXPADPOS ((size_t)BATCH * 102 * 154)
#define MAXPOS    ((size_t)BATCH * 100 * 152)
#define PSMAX 950

// ---------------- device buffers -------------------------------------------
__device__ __align__(16) __half g_Xin[MAXPADPOS * 256];
__device__ __align__(16) __half g_Xa [MAXPADPOS * 256];
__device__ __align__(16) __half g_Xb [MAXPADPOS * 256];
__device__ __align__(16) float g_convout[MAXPOS * 256];
__device__ __align__(16) __half g_Wth[8 * 256 * KDIM];
__device__ __align__(16) __half g_Wtl[8 * 256 * KDIM];
__device__ __align__(16) __half g_Whh[2 * 128 * KDIM];
__device__ __align__(16) __half g_Whl[2 * 128 * KDIM];
__device__ float g_hb[2 * 128];
__device__ float g_psA [256 * PSMAX];
__device__ float g_ps2A[256 * PSMAX];
__device__ float g_mean[256];
__device__ float g_rstd[256];

__device__ __forceinline__ void h_split(float v, __half& h, __half& l) {
    h = __float2half(v);
    l = __float2half(v - __half2float(h));
}

// ---------------- PTX helpers ----------------------------------------------
__device__ __forceinline__ uint32_t smem_to_u32(const void* p) {
    uint32_t a;
    asm("{ .reg .u64 t; cvta.to.shared.u64 t, %1; cvt.u32.u64 %0, t; }"
        : "=r"(a) : "l"(p));
    return a;
}
#define CP_ASYNC16(dst, src) \
    asm volatile("cp.async.cg.shared.global [%0], [%1], 16;" \
                 :: "r"(dst), "l"(src))
#define CP_COMMIT() asm volatile("cp.async.commit_group;" ::: "memory")
#define CP_WAIT(n)  asm volatile("cp.async.wait_group %0;" :: "n"(n) : "memory")

__device__ __forceinline__ void ldsm4(uint32_t (&r)[4], uint32_t a) {
    asm volatile("ldmatrix.sync.aligned.m8n8.x4.shared.b16 {%0,%1,%2,%3}, [%4];"
        : "=r"(r[0]), "=r"(r[1]), "=r"(r[2]), "=r"(r[3]) : "r"(a));
}
__device__ __forceinline__ void mma16816(float* d, const uint32_t* a, const uint32_t* b) {
    asm volatile(
        "mma.sync.aligned.m16n8k16.row.col.f32.f16.f16.f32 "
        "{%0,%1,%2,%3}, {%4,%5,%6,%7}, {%8,%9}, {%0,%1,%2,%3};"
        : "+f"(d[0]), "+f"(d[1]), "+f"(d[2]), "+f"(d[3])
        : "r"(a[0]), "r"(a[1]), "r"(a[2]), "r"(a[3]), "r"(b[0]), "r"(b[1]));
}

// ---------------- prep kernels ---------------------------------------------
__global__ void prep_weights_kernel(const float* __restrict__ cls_w,
                                    const float* __restrict__ box_w)
{
    long idx = (long)blockIdx.x * blockDim.x + threadIdx.x;
    if (idx >= 8L * 256 * KDIM) return;
    int j = (int)(idx / (256 * KDIM));
    int rem = (int)(idx - (long)j * 256 * KDIM);
    int m = rem / KDIM, k = rem - m * KDIM;
    int tap = k >> 8, ci = k & 255;
    const float* src = (j < 4) ? cls_w + (long)j * 256 * KDIM
                               : box_w + (long)(j - 4) * 256 * KDIM;
    float v = src[(m * 256 + ci) * 9 + tap];
    h_split(v, g_Wth[idx], g_Wtl[idx]);
}

__global__ void prep_heads_kernel(const float* __restrict__ logits_w,
                                  const float* __restrict__ logits_b,
                                  const float* __restrict__ ctr_w,
                                  const float* __restrict__ ctr_b,
                                  const float* __restrict__ reg_w,
                                  const float* __restrict__ reg_b)
{
    long idx = (long)blockIdx.x * blockDim.x + threadIdx.x;
    if (idx >= 2L * 128 * KDIM) return;
    int which = (int)(idx / (128 * KDIM));
    int rem = (int)(idx - (long)which * 128 * KDIM);
    int m = rem / KDIM, k = rem - m * KDIM;
    int tap = k >> 8, ci = k & 255;
    float v = 0.f;
    if (which == 0) {
        if (m < 80)       v = logits_w[(m * 256 + ci) * 9 + tap];
        else if (m == 80) v = ctr_w[ci * 9 + tap];
    } else {
        if (m < 4) v = reg_w[(m * 256 + ci) * 9 + tap];
    }
    h_split(v, g_Whh[idx], g_Whl[idx]);
    if (k == 0) {
        float bv = 0.f;
        if (which == 0) { if (m < 80) bv = logits_b[m]; else if (m == 80) bv = ctr_b[0]; }
        else            { if (m < 4)  bv = reg_b[m]; }
        g_hb[which * 128 + m] = bv;
    }
}

// Interior: NCHW f32 feat -> padded NHWC fp16 (Xin), 8 channels per thread,
// warp-contiguous positions (coalesced reads). Tail: zero borders of all 3.
__global__ void prep_act_kernel(const float* __restrict__ feat, int H, int W)
{
    const int HW = H * W;
    const int NP = BATCH * HW;
    const int Hp = H + 2, Wp = W + 2;
    const long nInt = (long)NP * 32;
    const int cnt = 2 * Wp + 2 * H;
    const long nBor = (long)BATCH * cnt * 32;
    long idx = (long)blockIdx.x * blockDim.x + threadIdx.x;
    if (idx < nInt) {
        int g = (int)(idx / NP);
        int p = (int)(idx - (long)g * NP);
        int b = p / HW, hw = p - b * HW;
        int y = hw / W, x = hw - y * W;
        const float* src = feat + ((long)b * 256 + g * 8) * HW + hw;
        __half hh[8];
#pragma unroll
        for (int i = 0; i < 8; i++) hh[i] = __float2half(src[(long)i * HW]);
        long a = (((long)b * Hp + y + 1) * Wp + x + 1) * 256 + g * 8;
        *(uint4*)(g_Xin + a) = *(const uint4*)hh;
        return;
    }
    idx -= nInt;
    if (idx >= 3 * nBor) return;
    int buf = (int)(idx / nBor);
    long r0 = idx - (long)buf * nBor;
    int b = (int)(r0 / (cnt * 32));
    int r = (int)(r0 - (long)b * cnt * 32);
    int i = r >> 5, q = r & 31;
    int y, x;
    if (i < Wp)              { y = 0;      x = i; }
    else if (i < 2 * Wp)     { y = Hp - 1; x = i - Wp; }
    else if (i < 2 * Wp + H) { y = 1 + (i - 2 * Wp);     x = 0; }
    else                     { y = 1 + (i - 2 * Wp - H); x = Wp - 1; }
    long a = (((long)b * Hp + y) * Wp + x) * 256 + q * 8;
    __half* dst = (buf == 0) ? g_Xin : (buf == 1) ? g_Xa : g_Xb;
    *(uint4*)(dst + a) = make_uint4(0, 0, 0, 0);
}

// ---------------- conv via mma.sync ----------------------------------------
// Stage: 3 tiles (Wh, Wl, X) of [128 rows][32 halfs], row stride 40 halfs
// (80 B, 16B-aligned, ldmatrix conflict-free). 3-slot ring, 2 groups in flight.
#define ROWB 80
#define TILE_BYTES (128 * ROWB)          // 10240
#define STAGE_B (3 * TILE_BYTES)         // 30720
#define RING 3
#define DYN_SMEM (RING * STAGE_B + 512 + 64)

__global__ __launch_bounds__(256, 2) void conv_mma_kernel(
    const __half* __restrict__ Wh, const __half* __restrict__ Wl,
    const float* __restrict__ bias,
    const __half* __restrict__ Xp,
    float* __restrict__ convout, float* __restrict__ dout,
    const float* __restrict__ scales, int lvl,
    int H, int W, int mode, long out_boff, long lvl_off)
{
    const int Hp = H + 2, Wp = W + 2, HW = H * W;
    const int N = BATCH * HW;
    const int n0 = blockIdx.x * 128;
    const int m0 = blockIdx.y * 128;
    const int tid = threadIdx.x, wid = tid >> 5, lid = tid & 31;

    extern __shared__ char dsm[];
    const uint32_t sb0 = smem_to_u32(dsm);
    int* sbase = (int*)(dsm + RING * STAGE_B);

    if (tid < 128) {
        int p = n0 + tid;
        if (p >= N) p = N - 1;
        int b = p / HW, hw = p - b * HW;
        int y = hw / W, x = hw - y * W;
        sbase[tid] = ((b * Hp + y) * Wp + x) * 256;
    }
    __syncthreads();

    // Per-thread load channels: 6 cp.async (16B each) per stage.
    const __half* gbase[6];
    uint32_t sdst[6];
    bool isA[6];
#pragma unroll
    for (int c = 0; c < 6; c++) {
        int id = c * 256 + tid;        // 0..1535
        int tile = id >> 9;            // 0:Wh 1:Wl 2:X
        int e = id & 511;
        int row = e >> 2, c4 = e & 3;
        isA[c] = (tile < 2);
        if (tile == 0)      gbase[c] = Wh + (long)(m0 + row) * KDIM + c4 * 8;
        else if (tile == 1) gbase[c] = Wl + (long)(m0 + row) * KDIM + c4 * 8;
        else                gbase[c] = Xp + (long)sbase[row] + c4 * 8;
        sdst[c] = sb0 + tile * TILE_BYTES + row * ROWB + c4 * 16;
    }

    const int NSTAGE = KDIM / 32;      // 72
    const int wm = wid & 3, wn = wid >> 2;
    const int Meff = (mode == 0) ? 128 : ((mode == 1) ? 85 : 4);
    const bool um0 = (wm * 32) < Meff;
    const bool um1 = (wm * 32 + 16) < Meff;

    float acc[2][8][4];
#pragma unroll
    for (int i = 0; i < 2; i++)
#pragma unroll
        for (int j = 0; j < 8; j++)
#pragma unroll
            for (int k = 0; k < 4; k++) acc[i][j][k] = 0.f;

    auto issue = [&](int s) {
        const uint32_t boff = (uint32_t)(s % RING) * STAGE_B;
        const int kA = s * 32;
        const int tap = s >> 3;
        const int kB = ((tap / 3) * Wp + (tap % 3)) * 256 + (s & 7) * 32;
#pragma unroll
        for (int c = 0; c < 6; c++)
            CP_ASYNC16(sdst[c] + boff, gbase[c] + (isA[c] ? kA : kB));
        CP_COMMIT();
    };

    issue(0); issue(1);
    for (int s = 0; s < NSTAGE; s++) {
        if (s == NSTAGE - 1) { CP_WAIT(0); } else { CP_WAIT(1); }
        __syncthreads();
        if (s + 2 < NSTAGE) issue(s + 2);

        const uint32_t tb = sb0 + (uint32_t)(s % RING) * STAGE_B;
        const uint32_t Ahb = tb, Alb = tb + TILE_BYTES, Bhb = tb + 2 * TILE_BYTES;

#pragma unroll
        for (int sl = 0; sl < 2; sl++) {
            uint32_t ah[2][4], al[2][4];
            if (um0) {
                uint32_t ao = (uint32_t)((wm * 32 + (lid & 15)) * ROWB
                                         + (sl * 16 + (lid >> 4) * 8) * 2);
                ldsm4(ah[0], Ahb + ao);
                ldsm4(al[0], Alb + ao);
            }
            if (um1) {
                uint32_t ao = (uint32_t)((wm * 32 + 16 + (lid & 15)) * ROWB
                                         + (sl * 16 + (lid >> 4) * 8) * 2);
                ldsm4(ah[1], Ahb + ao);
                ldsm4(al[1], Alb + ao);
            }
#pragma unroll
            for (int ng = 0; ng < 4; ng++) {
                const int q = lid >> 3;
                uint32_t bo = (uint32_t)((wn * 64 + ng * 16 + (q >> 1) * 8 + (lid & 7)) * ROWB
                                         + (sl * 16 + (q & 1) * 8) * 2);
                uint32_t bh[4];
                ldsm4(bh, Bhb + bo);
                if (um0) {
#pragma unroll
                    for (int h = 0; h < 2; h++) {
                        float* d = acc[0][ng * 2 + h];
                        mma16816(d, ah[0], &bh[h * 2]);
                        mma16816(d, al[0], &bh[h * 2]);
                    }
                }
                if (um1) {
#pragma unroll
                    for (int h = 0; h < 2; h++) {
                        float* d = acc[1][ng * 2 + h];
                        mma16816(d, ah[1], &bh[h * 2]);
                        mma16816(d, al[1], &bh[h * 2]);
                    }
                }
            }
        }
    }
    __syncthreads();   // all warps done reading smem before sred reuse

    // ---------------- epilogue ----------------
    const float sc = (mode == 2) ? scales[lvl] : 0.f;
    const int b0 = n0 / HW;
    float* sred = (float*)dsm;           // 96 floats: s[48], s2[48]
    float ts[12], ts2[12];
    if (mode == 0) {
        if (tid < 96) sred[tid] = 0.f;
#pragma unroll
        for (int i = 0; i < 12; i++) { ts[i] = 0.f; ts2[i] = 0.f; }
        __syncthreads();
    }

#pragma unroll
    for (int mi = 0; mi < 2; mi++) {
        if (!(mi == 0 ? um0 : um1)) continue;
        const int mlo = m0 + wm * 32 + mi * 16 + (lid >> 2);
        const float bv0 = bias[mlo];
        const float bv1 = bias[mlo + 8];
#pragma unroll
        for (int ng = 0; ng < 4; ng++) {
#pragma unroll
            for (int h = 0; h < 2; h++) {
                const float* d = acc[mi][ng * 2 + h];
                const int n = n0 + wn * 64 + ng * 16 + h * 8 + 2 * (lid & 3);
#pragma unroll
                for (int e = 0; e < 4; e++) {
                    const int p = n + (e & 1);
                    const int half_ = (e >> 1);
                    const int m = mlo + half_ * 8;
                    if (p >= N) continue;
                    float v = d[e] + (half_ ? bv1 : bv0);
                    if (mode == 0) {
                        __stcs(&convout[(size_t)p * 256 + m], v);
                        int db = p / HW - b0;
                        int si = (mi * 2 + half_) * 3 + db;
                        ts[si] += v; ts2[si] += v * v;
                    } else {
                        int b = p / HW, hw = p - b * HW;
                        long ob = (long)b * out_boff + lvl_off;
                        if (mode == 1) {
                            if (m < 80)       __stcs(&dout[ob + (long)m * HW + hw], v);
                            else if (m == 80) __stcs(&dout[ob + 84L * HW + hw], v);
                        } else {
                            if (m < 4) __stcs(&dout[ob + (long)(80 + m) * HW + hw],
                                              expf(sc * v));
                        }
                    }
                }
            }
        }
    }

    if (mode == 0) {
#pragma unroll
        for (int i = 0; i < 12; i++) {
            if (ts[i] == 0.f && ts2[i] == 0.f) continue;
            int db = i % 3, q = i / 3;
            int half_ = q & 1, mi = q >> 1;
            int gl = wm * 4 + mi * 2 + half_;
            atomicAdd(&sred[db * 16 + gl], ts[i]);
            atomicAdd(&sred[48 + db * 16 + gl], ts2[i]);
        }
        __syncthreads();
        if (tid < 48) {
            int db = tid >> 4, gl = tid & 15;
            int b = b0 + db;
            if (b < BATCH) {
                int g = (m0 >> 3) + gl;
                g_psA [((b * 32) + g) * PSMAX + blockIdx.x] = sred[tid];
                g_ps2A[((b * 32) + g) * PSMAX + blockIdx.x] = sred[48 + tid];
            }
        }
    }
}

// ---------------- GroupNorm stage 2 + apply ---------------------------------
__global__ __launch_bounds__(256) void gn_stats2_kernel(int HW, int nblk)
{
    const int bg = blockIdx.x;
    const int b = bg >> 5;
    const int N = BATCH * HW;
    float s = 0.f, s2 = 0.f;
    for (int nb = threadIdx.x; nb < nblk; nb += 256) {
        int p0 = nb * 128;
        int bfirst = p0 / HW;
        int pl = p0 + 127; if (pl >= N) pl = N - 1;
        int blast = pl / HW;
        if (b >= bfirst && b <= blast) {
            s  += g_psA [bg * PSMAX + nb];
            s2 += g_ps2A[bg * PSMAX + nb];
        }
    }
    __shared__ float ss[256], ss2[256];
    ss[threadIdx.x] = s; ss2[threadIdx.x] = s2;
    __syncthreads();
    for (int o = 128; o > 0; o >>= 1) {
        if (threadIdx.x < o) {
            ss[threadIdx.x]  += ss[threadIdx.x + o];
            ss2[threadIdx.x] += ss2[threadIdx.x + o];
        }
        __syncthreads();
    }
    if (threadIdx.x == 0) {
        float cnt = 8.f * HW;
        float mean = ss[0] / cnt;
        float var  = ss2[0] / cnt - mean * mean;
        g_mean[bg] = mean;
        g_rstd[bg] = rsqrtf(var + 1e-5f);
    }
}

// GN apply + ReLU: one thread per (position, group) = 8 channels.
__global__ __launch_bounds__(256) void gn_apply_kernel(
    const float* __restrict__ co, __half* __restrict__ xh,
    const float* __restrict__ gamma, const float* __restrict__ beta,
    int H, int W)
{
    const int HW = H * W;
    long idx = (long)blockIdx.x * blockDim.x + threadIdx.x;
    if (idx >= (long)BATCH * HW * 32) return;
    int g = (int)(idx & 31);
    int p = (int)(idx >> 5);
    int b = p / HW, hw = p - b * HW;
    int y = hw / W, x = hw - y * W;
    const int bg = b * 32 + g;
    const float mean = g_mean[bg], rstd = g_rstd[bg];
    const float* src = co + (size_t)p * 256 + g * 8;
    float4 v0 = __ldcs((const float4*)src);
    float4 v1 = __ldcs((const float4*)(src + 4));
    float vv[8] = {v0.x, v0.y, v0.z, v0.w, v1.x, v1.y, v1.z, v1.w};
    __half hh[8];
#pragma unroll
    for (int i = 0; i < 8; i++) {
        int c = g * 8 + i;
        float v = (vv[i] - mean) * rstd * gamma[c] + beta[c];
        hh[i] = __float2half(v > 0.f ? v : 0.f);
    }
    long a = (((long)b * (H + 2) + y + 1) * (W + 2) + x + 1) * 256 + g * 8;
    *(uint4*)(xh + a) = *(const uint4*)hh;
}

// All-level FCOS locations in one launch.
__global__ __launch_bounds__(256) void loc_all_kernel(float* __restrict__ out, long base)
{
    static const int WS[5]  = {152, 76, 38, 19, 10};
    static const int STR[5] = {8, 16, 32, 64, 128};
    static const int OFF[5] = {0, 15200, 19000, 19950, 20197};
    int idx = blockIdx.x * blockDim.x + threadIdx.x;
    if (idx >= 20267) return;
    int l = 4;
    if (idx < 15200) l = 0;
    else if (idx < 19000) l = 1;
    else if (idx < 19950) l = 2;
    else if (idx < 20197) l = 3;
    int r = idx - OFF[l];
    int y = r / WS[l], x = r - y * WS[l];
    out[base + 2 * idx]     = (float)(x * STR[l] + STR[l] / 2);
    out[base + 2 * idx + 1] = (float)(y * STR[l] + STR[l] / 2);
}

// ---------------------------------------------------------------------------
extern "C" void kernel_launch(void* const* d_in, const int* in_sizes, int n_in,
                              void* d_out, int out_size)
{
    (void)in_sizes; (void)n_in; (void)out_size;
    const float* feats[5];
    for (int i = 0; i < 5; i++) feats[i] = (const float*)d_in[i];
    const float* cls_w    = (const float*)d_in[5];
    const float* cls_b    = (const float*)d_in[6];
    const float* cls_gn_g = (const float*)d_in[7];
    const float* cls_gn_b = (const float*)d_in[8];
    const float* box_w    = (const float*)d_in[9];
    const float* box_b    = (const float*)d_in[10];
    const float* box_gn_g = (const float*)d_in[11];
    const float* box_gn_b = (const float*)d_in[12];
    const float* logits_w = (const float*)d_in[13];
    const float* logits_b = (const float*)d_in[14];
    const float* ctr_w    = (const float*)d_in[15];
    const float* ctr_b    = (const float*)d_in[16];
    const float* reg_w    = (const float*)d_in[17];
    const float* reg_b    = (const float*)d_in[18];
    const float* scales   = (const float*)d_in[19];
    float* out = (float*)d_out;

    cudaFuncSetAttribute(conv_mma_kernel,
                         cudaFuncAttributeMaxDynamicSharedMemorySize, DYN_SMEM);

    __half *Xin, *Xa, *Xb, *Wth, *Wtl, *Whh, *Whl;
    float *convout, *hb;
    cudaGetSymbolAddress((void**)&Xin, g_Xin);
    cudaGetSymbolAddress((void**)&Xa, g_Xa);
    cudaGetSymbolAddress((void**)&Xb, g_Xb);
    cudaGetSymbolAddress((void**)&Wth, g_Wth);
    cudaGetSymbolAddress((void**)&Wtl, g_Wtl);
    cudaGetSymbolAddress((void**)&Whh, g_Whh);
    cudaGetSymbolAddress((void**)&Whl, g_Whl);
    cudaGetSymbolAddress((void**)&convout, g_convout);
    cudaGetSymbolAddress((void**)&hb, g_hb);

    static const int HS[5]  = {100, 50, 25, 13, 7};
    static const int WS[5]  = {152, 76, 38, 19, 10};

    long out_boff = 0;
    for (int l = 0; l < 5; l++) out_boff += 85L * HS[l] * WS[l];
    const long locs_base = (long)BATCH * out_boff;

    prep_weights_kernel<<<(int)((8L * 256 * KDIM + 255) / 256), 256>>>(cls_w, box_w);
    prep_heads_kernel<<<(int)((2L * 128 * KDIM + 255) / 256), 256>>>(
        logits_w, logits_b, ctr_w, ctr_b, reg_w, reg_b);

    long lvl_off = 0;
    for (int l = 0; l < 5; l++) {
        const int H = HS[l], W = WS[l], HW = H * W;
        const int N = BATCH * HW;
        const int nblk = (N + 127) / 128;
        const int Hp = H + 2, Wp = W + 2;
        const int cnt = 2 * Wp + 2 * H;
        const long pa_tot = (long)N * 32 + 3L * BATCH * cnt * 32;
        const int pg = (int)((pa_tot + 255) / 256);
        const int ag = (int)(((long)N * 32 + 255) / 256);

        prep_act_kernel<<<pg, 256>>>(feats[l], H, W);

        __half* srcs[4] = {Xin, Xa, Xb, Xa};
        __half* dsts[4] = {Xa, Xb, Xa, Xb};

        dim3 gconv(nblk, 2);
        dim3 ghead(nblk, 1);

        for (int tower = 0; tower < 2; tower++) {
            const __half* wth = Wth + (long)tower * 4 * 256 * KDIM;
            const __half* wtl = Wtl + (long)tower * 4 * 256 * KDIM;
            const float* btower = tower ? box_b : cls_b;
            const float* gg = tower ? box_gn_g : cls_gn_g;
            const float* gb = tower ? box_gn_b : cls_gn_b;
            for (int i = 0; i < 4; i++) {
                conv_mma_kernel<<<gconv, 256, DYN_SMEM>>>(
                    wth + (long)i * 256 * KDIM, wtl + (long)i * 256 * KDIM,
                    btower + i * 256, srcs[i],
                    convout, nullptr, scales, l, H, W, 0, 0, 0);
                gn_stats2_kernel<<<256, 256>>>(HW, nblk);
                gn_apply_kernel<<<ag, 256>>>(convout, dsts[i],
                                             gg + i * 256, gb + i * 256, H, W);
            }
            if (tower == 0) {
                conv_mma_kernel<<<ghead, 256, DYN_SMEM>>>(
                    Whh, Whl, hb, Xb, nullptr, out, scales, l,
                    H, W, 1, out_boff, lvl_off);
            } else {
                conv_mma_kernel<<<ghead, 256, DYN_SMEM>>>(
                    Whh + (long)128 * KDIM, Whl + (long)128 * KDIM, hb + 128,
                    Xb, nullptr, out, scales, l,
                    H, W, 2, out_boff, lvl_off);
            }
        }
        lvl_off += 85L * HW;
    }
    loc_all_kernel<<<(20267 + 255) / 256, 256>>>(out, locs_base);
}

// round 11
// speedup vs baseline: 1.8091x; 1.4762x over previous
#include <cuda_runtime.h>
#include <cuda_fp16.h>
#include <math.h>
#include <stdint.h>

// ===========================================================================
// FCOS head via mma.sync fp16 tensor cores (compute_100-safe; no tcgen05).
// Conv3x3 as implicit GEMM, plain fp16 W and X (rel_err ~6e-5, gate 1e-3).
// 4-slot cp.async ring (3 in flight), one __syncthreads per stage. GN stats
// fused into conv epilogue (deterministic). Head convs skip dead M-rows.
// ===========================================================================

#define BATCH 8
#define KDIM 2304
#define MAXPADPOS ((size_t)BATCH * 102 * 154)
#define MAXPOS    ((size_t)BATCH * 100 * 152)
#define PSMAX 950

// ---------------- device buffers -------------------------------------------
__device__ __align__(16) __half g_Xin[MAXPADPOS * 256];
__device__ __align__(16) __half g_Xa [MAXPADPOS * 256];
__device__ __align__(16) __half g_Xb [MAXPADPOS * 256];
__device__ __align__(16) float g_convout[MAXPOS * 256];
__device__ __align__(16) __half g_Wt[8 * 256 * KDIM];
__device__ __align__(16) __half g_Wh[2 * 128 * KDIM];
__device__ float g_hb[2 * 128];
__device__ float g_psA [256 * PSMAX];
__device__ float g_ps2A[256 * PSMAX];
__device__ float g_mean[256];
__device__ float g_rstd[256];

// ---------------- PTX helpers ----------------------------------------------
__device__ __forceinline__ uint32_t smem_to_u32(const void* p) {
    uint32_t a;
    asm("{ .reg .u64 t; cvta.to.shared.u64 t, %1; cvt.u32.u64 %0, t; }"
        : "=r"(a) : "l"(p));
    return a;
}
#define CP_ASYNC16(dst, src) \
    asm volatile("cp.async.cg.shared.global [%0], [%1], 16;" \
                 :: "r"(dst), "l"(src))
#define CP_COMMIT() asm volatile("cp.async.commit_group;" ::: "memory")
#define CP_WAIT(n)  asm volatile("cp.async.wait_group %0;" :: "n"(n) : "memory")

__device__ __forceinline__ void ldsm4(uint32_t (&r)[4], uint32_t a) {
    asm volatile("ldmatrix.sync.aligned.m8n8.x4.shared.b16 {%0,%1,%2,%3}, [%4];"
        : "=r"(r[0]), "=r"(r[1]), "=r"(r[2]), "=r"(r[3]) : "r"(a));
}
__device__ __forceinline__ void mma16816(float* d, const uint32_t* a, const uint32_t* b) {
    asm volatile(
        "mma.sync.aligned.m16n8k16.row.col.f32.f16.f16.f32 "
        "{%0,%1,%2,%3}, {%4,%5,%6,%7}, {%8,%9}, {%0,%1,%2,%3};"
        : "+f"(d[0]), "+f"(d[1]), "+f"(d[2]), "+f"(d[3])
        : "r"(a[0]), "r"(a[1]), "r"(a[2]), "r"(a[3]), "r"(b[0]), "r"(b[1]));
}

// ---------------- prep kernels ---------------------------------------------
__global__ void prep_weights_kernel(const float* __restrict__ cls_w,
                                    const float* __restrict__ box_w)
{
    long idx = (long)blockIdx.x * blockDim.x + threadIdx.x;
    if (idx >= 8L * 256 * KDIM) return;
    int j = (int)(idx / (256 * KDIM));
    int rem = (int)(idx - (long)j * 256 * KDIM);
    int m = rem / KDIM, k = rem - m * KDIM;
    int tap = k >> 8, ci = k & 255;
    const float* src = (j < 4) ? cls_w + (long)j * 256 * KDIM
                               : box_w + (long)(j - 4) * 256 * KDIM;
    g_Wt[idx] = __float2half(src[(m * 256 + ci) * 9 + tap]);
}

__global__ void prep_heads_kernel(const float* __restrict__ logits_w,
                                  const float* __restrict__ logits_b,
                                  const float* __restrict__ ctr_w,
                                  const float* __restrict__ ctr_b,
                                  const float* __restrict__ reg_w,
                                  const float* __restrict__ reg_b)
{
    long idx = (long)blockIdx.x * blockDim.x + threadIdx.x;
    if (idx >= 2L * 128 * KDIM) return;
    int which = (int)(idx / (128 * KDIM));
    int rem = (int)(idx - (long)which * 128 * KDIM);
    int m = rem / KDIM, k = rem - m * KDIM;
    int tap = k >> 8, ci = k & 255;
    float v = 0.f;
    if (which == 0) {
        if (m < 80)       v = logits_w[(m * 256 + ci) * 9 + tap];
        else if (m == 80) v = ctr_w[ci * 9 + tap];
    } else {
        if (m < 4) v = reg_w[(m * 256 + ci) * 9 + tap];
    }
    g_Wh[idx] = __float2half(v);
    if (k == 0) {
        float bv = 0.f;
        if (which == 0) { if (m < 80) bv = logits_b[m]; else if (m == 80) bv = ctr_b[0]; }
        else            { if (m < 4)  bv = reg_b[m]; }
        g_hb[which * 128 + m] = bv;
    }
}

// Interior: NCHW f32 feat -> padded NHWC fp16 (Xin), 8 channels per thread,
// warp-contiguous positions (coalesced reads). Tail: zero borders of all 3.
__global__ void prep_act_kernel(const float* __restrict__ feat, int H, int W)
{
    const int HW = H * W;
    const int NP = BATCH * HW;
    const int Hp = H + 2, Wp = W + 2;
    const long nInt = (long)NP * 32;
    const int cnt = 2 * Wp + 2 * H;
    const long nBor = (long)BATCH * cnt * 32;
    long idx = (long)blockIdx.x * blockDim.x + threadIdx.x;
    if (idx < nInt) {
        int g = (int)(idx / NP);
        int p = (int)(idx - (long)g * NP);
        int b = p / HW, hw = p - b * HW;
        int y = hw / W, x = hw - y * W;
        const float* src = feat + ((long)b * 256 + g * 8) * HW + hw;
        __half hh[8];
#pragma unroll
        for (int i = 0; i < 8; i++) hh[i] = __float2half(src[(long)i * HW]);
        long a = (((long)b * Hp + y + 1) * Wp + x + 1) * 256 + g * 8;
        *(uint4*)(g_Xin + a) = *(const uint4*)hh;
        return;
    }
    idx -= nInt;
    if (idx >= 3 * nBor) return;
    int buf = (int)(idx / nBor);
    long r0 = idx - (long)buf * nBor;
    int b = (int)(r0 / (cnt * 32));
    int r = (int)(r0 - (long)b * cnt * 32);
    int i = r >> 5, q = r & 31;
    int y, x;
    if (i < Wp)              { y = 0;      x = i; }
    else if (i < 2 * Wp)     { y = Hp - 1; x = i - Wp; }
    else if (i < 2 * Wp + H) { y = 1 + (i - 2 * Wp);     x = 0; }
    else                     { y = 1 + (i - 2 * Wp - H); x = Wp - 1; }
    long a = (((long)b * Hp + y) * Wp + x) * 256 + q * 8;
    __half* dst = (buf == 0) ? g_Xin : (buf == 1) ? g_Xa : g_Xb;
    *(uint4*)(dst + a) = make_uint4(0, 0, 0, 0);
}

// ---------------- conv via mma.sync ----------------------------------------
// Stage: 2 tiles (W, X) of [128 rows][32 halfs], row stride 40 halfs
// (80 B, 16B-aligned, ldmatrix conflict-free). 4-slot ring, 3 in flight.
#define ROWB 80
#define TILE_BYTES (128 * ROWB)          // 10240
#define STAGE_B (2 * TILE_BYTES)         // 20480
#define RING 4
#define DYN_SMEM (RING * STAGE_B + 512 + 64)

__global__ __launch_bounds__(256, 2) void conv_mma_kernel(
    const __half* __restrict__ Wt,
    const float* __restrict__ bias,
    const __half* __restrict__ Xp,
    float* __restrict__ convout, float* __restrict__ dout,
    const float* __restrict__ scales, int lvl,
    int H, int W, int mode, long out_boff, long lvl_off)
{
    const int Hp = H + 2, Wp = W + 2, HW = H * W;
    const int N = BATCH * HW;
    const int n0 = blockIdx.x * 128;
    const int m0 = blockIdx.y * 128;
    const int tid = threadIdx.x, wid = tid >> 5, lid = tid & 31;

    extern __shared__ char dsm[];
    const uint32_t sb0 = smem_to_u32(dsm);
    int* sbase = (int*)(dsm + RING * STAGE_B);

    if (tid < 128) {
        int p = n0 + tid;
        if (p >= N) p = N - 1;
        int b = p / HW, hw = p - b * HW;
        int y = hw / W, x = hw - y * W;
        sbase[tid] = ((b * Hp + y) * Wp + x) * 256;
    }
    __syncthreads();

    // Per-thread load channels: 4 cp.async (16B each) per stage.
    const __half* gbase[4];
    uint32_t sdst[4];
    bool isA[4];
#pragma unroll
    for (int c = 0; c < 4; c++) {
        int id = c * 256 + tid;        // 0..1023
        int tile = id >> 9;            // 0:W 1:X
        int e = id & 511;
        int row = e >> 2, c4 = e & 3;
        isA[c] = (tile == 0);
        if (tile == 0) gbase[c] = Wt + (long)(m0 + row) * KDIM + c4 * 8;
        else           gbase[c] = Xp + (long)sbase[row] + c4 * 8;
        sdst[c] = sb0 + tile * TILE_BYTES + row * ROWB + c4 * 16;
    }

    const int NSTAGE = KDIM / 32;      // 72
    const int wm = wid & 3, wn = wid >> 2;
    const int Meff = (mode == 0) ? 128 : ((mode == 1) ? 85 : 4);
    const bool um0 = (wm * 32) < Meff;
    const bool um1 = (wm * 32 + 16) < Meff;

    float acc[2][8][4];
#pragma unroll
    for (int i = 0; i < 2; i++)
#pragma unroll
        for (int j = 0; j < 8; j++)
#pragma unroll
            for (int k = 0; k < 4; k++) acc[i][j][k] = 0.f;

    auto issue = [&](int s) {
        const uint32_t boff = (uint32_t)(s % RING) * STAGE_B;
        const int kA = s * 32;
        const int tap = s >> 3;
        const int kB = ((tap / 3) * Wp + (tap % 3)) * 256 + (s & 7) * 32;
#pragma unroll
        for (int c = 0; c < 4; c++)
            CP_ASYNC16(sdst[c] + boff, gbase[c] + (isA[c] ? kA : kB));
        CP_COMMIT();
    };

    issue(0); issue(1); issue(2);
    for (int s = 0; s < NSTAGE; s++) {
        if (s + 2 < NSTAGE)      { CP_WAIT(2); }
        else if (s + 1 < NSTAGE) { CP_WAIT(1); }
        else                     { CP_WAIT(0); }
        __syncthreads();
        if (s + 3 < NSTAGE) issue(s + 3);

        const uint32_t tb = sb0 + (uint32_t)(s % RING) * STAGE_B;
        const uint32_t Ab = tb, Bb = tb + TILE_BYTES;

#pragma unroll
        for (int sl = 0; sl < 2; sl++) {
            uint32_t ah[2][4];
            if (um0) {
                uint32_t ao = (uint32_t)((wm * 32 + (lid & 15)) * ROWB
                                         + (sl * 16 + (lid >> 4) * 8) * 2);
                ldsm4(ah[0], Ab + ao);
            }
            if (um1) {
                uint32_t ao = (uint32_t)((wm * 32 + 16 + (lid & 15)) * ROWB
                                         + (sl * 16 + (lid >> 4) * 8) * 2);
                ldsm4(ah[1], Ab + ao);
            }
#pragma unroll
            for (int ng = 0; ng < 4; ng++) {
                const int q = lid >> 3;
                uint32_t bo = (uint32_t)((wn * 64 + ng * 16 + (q >> 1) * 8 + (lid & 7)) * ROWB
                                         + (sl * 16 + (q & 1) * 8) * 2);
                uint32_t bh[4];
                ldsm4(bh, Bb + bo);
                if (um0) {
#pragma unroll
                    for (int h = 0; h < 2; h++)
                        mma16816(acc[0][ng * 2 + h], ah[0], &bh[h * 2]);
                }
                if (um1) {
#pragma unroll
                    for (int h = 0; h < 2; h++)
                        mma16816(acc[1][ng * 2 + h], ah[1], &bh[h * 2]);
                }
            }
        }
    }
    __syncthreads();   // all warps done reading smem before sred reuse

    // ---------------- epilogue ----------------
    const float sc = (mode == 2) ? scales[lvl] : 0.f;
    const int b0 = n0 / HW;
    float* sred = (float*)dsm;           // 96 floats: s[48], s2[48]
    float ts[12], ts2[12];
    if (mode == 0) {
        if (tid < 96) sred[tid] = 0.f;
#pragma unroll
        for (int i = 0; i < 12; i++) { ts[i] = 0.f; ts2[i] = 0.f; }
        __syncthreads();
    }

#pragma unroll
    for (int mi = 0; mi < 2; mi++) {
        if (!(mi == 0 ? um0 : um1)) continue;
        const int mlo = m0 + wm * 32 + mi * 16 + (lid >> 2);
        const float bv0 = bias[mlo];
        const float bv1 = bias[mlo + 8];
#pragma unroll
        for (int ng = 0; ng < 4; ng++) {
#pragma unroll
            for (int h = 0; h < 2; h++) {
                const float* d = acc[mi][ng * 2 + h];
                const int n = n0 + wn * 64 + ng * 16 + h * 8 + 2 * (lid & 3);
#pragma unroll
                for (int e = 0; e < 4; e++) {
                    const int p = n + (e & 1);
                    const int half_ = (e >> 1);
                    const int m = mlo + half_ * 8;
                    if (p >= N) continue;
                    float v = d[e] + (half_ ? bv1 : bv0);
                    if (mode == 0) {
                        __stcs(&convout[(size_t)p * 256 + m], v);
                        int db = p / HW - b0;
                        int si = (mi * 2 + half_) * 3 + db;
                        ts[si] += v; ts2[si] += v * v;
                    } else {
                        int b = p / HW, hw = p - b * HW;
                        long ob = (long)b * out_boff + lvl_off;
                        if (mode == 1) {
                            if (m < 80)       __stcs(&dout[ob + (long)m * HW + hw], v);
                            else if (m == 80) __stcs(&dout[ob + 84L * HW + hw], v);
                        } else {
                            if (m < 4) __stcs(&dout[ob + (long)(80 + m) * HW + hw],
                                              expf(sc * v));
                        }
                    }
                }
            }
        }
    }

    if (mode == 0) {
#pragma unroll
        for (int i = 0; i < 12; i++) {
            if (ts[i] == 0.f && ts2[i] == 0.f) continue;
            int db = i % 3, q = i / 3;
            int half_ = q & 1, mi = q >> 1;
            int gl = wm * 4 + mi * 2 + half_;
            atomicAdd(&sred[db * 16 + gl], ts[i]);
            atomicAdd(&sred[48 + db * 16 + gl], ts2[i]);
        }
        __syncthreads();
        if (tid < 48) {
            int db = tid >> 4, gl = tid & 15;
            int b = b0 + db;
            if (b < BATCH) {
                int g = (m0 >> 3) + gl;
                g_psA [((b * 32) + g) * PSMAX + blockIdx.x] = sred[tid];
                g_ps2A[((b * 32) + g) * PSMAX + blockIdx.x] = sred[48 + tid];
            }
        }
    }
}

// ---------------- GroupNorm stage 2 + apply ---------------------------------
__global__ __launch_bounds__(256) void gn_stats2_kernel(int HW, int nblk)
{
    const int bg = blockIdx.x;
    const int b = bg >> 5;
    const int N = BATCH * HW;
    float s = 0.f, s2 = 0.f;
    for (int nb = threadIdx.x; nb < nblk; nb += 256) {
        int p0 = nb * 128;
        int bfirst = p0 / HW;
        int pl = p0 + 127; if (pl >= N) pl = N - 1;
        int blast = pl / HW;
        if (b >= bfirst && b <= blast) {
            s  += g_psA [bg * PSMAX + nb];
            s2 += g_ps2A[bg * PSMAX + nb];
        }
    }
    __shared__ float ss[256], ss2[256];
    ss[threadIdx.x] = s; ss2[threadIdx.x] = s2;
    __syncthreads();
    for (int o = 128; o > 0; o >>= 1) {
        if (threadIdx.x < o) {
            ss[threadIdx.x]  += ss[threadIdx.x + o];
            ss2[threadIdx.x] += ss2[threadIdx.x + o];
        }
        __syncthreads();
    }
    if (threadIdx.x == 0) {
        float cnt = 8.f * HW;
        float mean = ss[0] / cnt;
        float var  = ss2[0] / cnt - mean * mean;
        g_mean[bg] = mean;
        g_rstd[bg] = rsqrtf(var + 1e-5f);
    }
}

// GN apply + ReLU: one thread per (position, group) = 8 channels.
__global__ __launch_bounds__(256) void gn_apply_kernel(
    const float* __restrict__ co, __half* __restrict__ xh,
    const float* __restrict__ gamma, const float* __restrict__ beta,
    int H, int W)
{
    const int HW = H * W;
    long idx = (long)blockIdx.x * blockDim.x + threadIdx.x;
    if (idx >= (long)BATCH * HW * 32) return;
    int g = (int)(idx & 31);
    int p = (int)(idx >> 5);
    int b = p / HW, hw = p - b * HW;
    int y = hw / W, x = hw - y * W;
    const int bg = b * 32 + g;
    const float mean = g_mean[bg], rstd = g_rstd[bg];
    const float* src = co + (size_t)p * 256 + g * 8;
    float4 v0 = __ldcs((const float4*)src);
    float4 v1 = __ldcs((const float4*)(src + 4));
    float vv[8] = {v0.x, v0.y, v0.z, v0.w, v1.x, v1.y, v1.z, v1.w};
    __half hh[8];
#pragma unroll
    for (int i = 0; i < 8; i++) {
        int c = g * 8 + i;
        float v = (vv[i] - mean) * rstd * gamma[c] + beta[c];
        hh[i] = __float2half(v > 0.f ? v : 0.f);
    }
    long a = (((long)b * (H + 2) + y + 1) * (W + 2) + x + 1) * 256 + g * 8;
    *(uint4*)(xh + a) = *(const uint4*)hh;
}

// All-level FCOS locations in one launch.
__global__ __launch_bounds__(256) void loc_all_kernel(float* __restrict__ out, long base)
{
    static const int WS[5]  = {152, 76, 38, 19, 10};
    static const int STR[5] = {8, 16, 32, 64, 128};
    static const int OFF[5] = {0, 15200, 19000, 19950, 20197};
    int idx = blockIdx.x * blockDim.x + threadIdx.x;
    if (idx >= 20267) return;
    int l = 4;
    if (idx < 15200) l = 0;
    else if (idx < 19000) l = 1;
    else if (idx < 19950) l = 2;
    else if (idx < 20197) l = 3;
    int r = idx - OFF[l];
    int y = r / WS[l], x = r - y * WS[l];
    out[base + 2 * idx]     = (float)(x * STR[l] + STR[l] / 2);
    out[base + 2 * idx + 1] = (float)(y * STR[l] + STR[l] / 2);
}

// ---------------------------------------------------------------------------
extern "C" void kernel_launch(void* const* d_in, const int* in_sizes, int n_in,
                              void* d_out, int out_size)
{
    (void)in_sizes; (void)n_in; (void)out_size;
    const float* feats[5];
    for (int i = 0; i < 5; i++) feats[i] = (const float*)d_in[i];
    const float* cls_w    = (const float*)d_in[5];
    const float* cls_b    = (const float*)d_in[6];
    const float* cls_gn_g = (const float*)d_in[7];
    const float* cls_gn_b = (const float*)d_in[8];
    const float* box_w    = (const float*)d_in[9];
    const float* box_b    = (const float*)d_in[10];
    const float* box_gn_g = (const float*)d_in[11];
    const float* box_gn_b = (const float*)d_in[12];
    const float* logits_w = (const float*)d_in[13];
    const float* logits_b = (const float*)d_in[14];
    const float* ctr_w    = (const float*)d_in[15];
    const float* ctr_b    = (const float*)d_in[16];
    const float* reg_w    = (const float*)d_in[17];
    const float* reg_b    = (const float*)d_in[18];
    const float* scales   = (const float*)d_in[19];
    float* out = (float*)d_out;

    cudaFuncSetAttribute(conv_mma_kernel,
                         cudaFuncAttributeMaxDynamicSharedMemorySize, DYN_SMEM);

    __half *Xin, *Xa, *Xb, *Wt, *Wh;
    float *convout, *hb;
    cudaGetSymbolAddress((void**)&Xin, g_Xin);
    cudaGetSymbolAddress((void**)&Xa, g_Xa);
    cudaGetSymbolAddress((void**)&Xb, g_Xb);
    cudaGetSymbolAddress((void**)&Wt, g_Wt);
    cudaGetSymbolAddress((void**)&Wh, g_Wh);
    cudaGetSymbolAddress((void**)&convout, g_convout);
    cudaGetSymbolAddress((void**)&hb, g_hb);

    static const int HS[5]  = {100, 50, 25, 13, 7};
    static const int WS[5]  = {152, 76, 38, 19, 10};

    long out_boff = 0;
    for (int l = 0; l < 5; l++) out_boff += 85L * HS[l] * WS[l];
    const long locs_base = (long)BATCH * out_boff;

    prep_weights_kernel<<<(int)((8L * 256 * KDIM + 255) / 256), 256>>>(cls_w, box_w);
    prep_heads_kernel<<<(int)((2L * 128 * KDIM + 255) / 256), 256>>>(
        logits_w, logits_b, ctr_w, ctr_b, reg_w, reg_b);

    long lvl_off = 0;
    for (int l = 0; l < 5; l++) {
        const int H = HS[l], W = WS[l], HW = H * W;
        const int N = BATCH * HW;
        const int nblk = (N + 127) / 128;
        const int Hp = H + 2, Wp = W + 2;
        const int cnt = 2 * Wp + 2 * H;
        const long pa_tot = (long)N * 32 + 3L * BATCH * cnt * 32;
        const int pg = (int)((pa_tot + 255) / 256);
        const int ag = (int)(((long)N * 32 + 255) / 256);

        prep_act_kernel<<<pg, 256>>>(feats[l], H, W);

        __half* srcs[4] = {Xin, Xa, Xb, Xa};
        __half* dsts[4] = {Xa, Xb, Xa, Xb};

        dim3 gconv(nblk, 2);
        dim3 ghead(nblk, 1);

        for (int tower = 0; tower < 2; tower++) {
            const __half* wt = Wt + (long)tower * 4 * 256 * KDIM;
            const float* btower = tower ? box_b : cls_b;
            const float* gg = tower ? box_gn_g : cls_gn_g;
            const float* gb = tower ? box_gn_b : cls_gn_b;
            for (int i = 0; i < 4; i++) {
                conv_mma_kernel<<<gconv, 256, DYN_SMEM>>>(
                    wt + (long)i * 256 * KDIM, btower + i * 256, srcs[i],
                    convout, nullptr, scales, l, H, W, 0, 0, 0);
                gn_stats2_kernel<<<256, 256>>>(HW, nblk);
                gn_apply_kernel<<<ag, 256>>>(convout, dsts[i],
                                             gg + i * 256, gb + i * 256, H, W);
            }
            if (tower == 0) {
                conv_mma_kernel<<<ghead, 256, DYN_SMEM>>>(
                    Wh, hb, Xb, nullptr, out, scales, l,
                    H, W, 1, out_boff, lvl_off);
            } else {
                conv_mma_kernel<<<ghead, 256, DYN_SMEM>>>(
                    Wh + (long)128 * KDIM, hb + 128, Xb, nullptr, out, scales, l,
                    H, W, 2, out_boff, lvl_off);
            }
        }
        lvl_off += 85L * HW;
    }
    loc_all_kernel<<<(20267 + 255) / 256, 256>>>(out, locs_base);
}

// round 13
// speedup vs baseline: 2.1499x; 1.1884x over previous
#include <cuda_runtime.h>
#include <cuda_fp16.h>
#include <math.h>
#include <stdint.h>

// ===========================================================================
// FCOS head via mma.sync fp16 tensor cores (compute_100-safe; no tcgen05).
// Conv3x3 as implicit GEMM, plain fp16 W and X. R13 (= audited R12): K=64
// stages (36 barriers), race-free double buffer, cls+box towers fused per
// launch (grid y=4), fp16 convout, fused gn_apply and fused heads.
// ===========================================================================

#define BATCH 8
#define KDIM 2304
#define MAXPADPOS ((size_t)BATCH * 102 * 154)
#define MAXPOS    ((size_t)BATCH * 100 * 152)
#define PSMAX 950
#define CONVOFF ((size_t)MAXPOS * 256)

// ---------------- device buffers -------------------------------------------
__device__ __align__(16) __half g_Xin[MAXPADPOS * 256];
__device__ __align__(16) __half g_Xa1[MAXPADPOS * 256];
__device__ __align__(16) __half g_Xb1[MAXPADPOS * 256];
__device__ __align__(16) __half g_Xa2[MAXPADPOS * 256];
__device__ __align__(16) __half g_Xb2[MAXPADPOS * 256];
__device__ __align__(16) __half g_convout[2 * CONVOFF];
__device__ __align__(16) __half g_Wt[8 * 256 * KDIM];
__device__ __align__(16) __half g_Wh[2 * 128 * KDIM];
__device__ float g_hb[2 * 128];
__device__ float g_psA [512 * PSMAX];
__device__ float g_ps2A[512 * PSMAX];
__device__ float g_mean[512];
__device__ float g_rstd[512];

// ---------------- PTX helpers ----------------------------------------------
__device__ __forceinline__ uint32_t smem_to_u32(const void* p) {
    uint32_t a;
    asm("{ .reg .u64 t; cvta.to.shared.u64 t, %1; cvt.u32.u64 %0, t; }"
        : "=r"(a) : "l"(p));
    return a;
}
#define CP_ASYNC16(dst, src) \
    asm volatile("cp.async.cg.shared.global [%0], [%1], 16;" \
                 :: "r"(dst), "l"(src))
#define CP_COMMIT() asm volatile("cp.async.commit_group;" ::: "memory")
#define CP_WAIT0()  asm volatile("cp.async.wait_group 0;" ::: "memory")

__device__ __forceinline__ void ldsm4(uint32_t (&r)[4], uint32_t a) {
    asm volatile("ldmatrix.sync.aligned.m8n8.x4.shared.b16 {%0,%1,%2,%3}, [%4];"
        : "=r"(r[0]), "=r"(r[1]), "=r"(r[2]), "=r"(r[3]) : "r"(a));
}
__device__ __forceinline__ void mma16816(float* d, const uint32_t* a, const uint32_t* b) {
    asm volatile(
        "mma.sync.aligned.m16n8k16.row.col.f32.f16.f16.f32 "
        "{%0,%1,%2,%3}, {%4,%5,%6,%7}, {%8,%9}, {%0,%1,%2,%3};"
        : "+f"(d[0]), "+f"(d[1]), "+f"(d[2]), "+f"(d[3])
        : "r"(a[0]), "r"(a[1]), "r"(a[2]), "r"(a[3]), "r"(b[0]), "r"(b[1]));
}

// ---------------- prep kernels ---------------------------------------------
__global__ void prep_weights_kernel(const float* __restrict__ cls_w,
                                    const float* __restrict__ box_w)
{
    long idx = (long)blockIdx.x * blockDim.x + threadIdx.x;
    if (idx >= 8L * 256 * KDIM) return;
    int j = (int)(idx / (256 * KDIM));
    int rem = (int)(idx - (long)j * 256 * KDIM);
    int m = rem / KDIM, k = rem - m * KDIM;
    int tap = k >> 8, ci = k & 255;
    const float* src = (j < 4) ? cls_w + (long)j * 256 * KDIM
                               : box_w + (long)(j - 4) * 256 * KDIM;
    g_Wt[idx] = __float2half(src[(m * 256 + ci) * 9 + tap]);
}

__global__ void prep_heads_kernel(const float* __restrict__ logits_w,
                                  const float* __restrict__ logits_b,
                                  const float* __restrict__ ctr_w,
                                  const float* __restrict__ ctr_b,
                                  const float* __restrict__ reg_w,
                                  const float* __restrict__ reg_b)
{
    long idx = (long)blockIdx.x * blockDim.x + threadIdx.x;
    if (idx >= 2L * 128 * KDIM) return;
    int which = (int)(idx / (128 * KDIM));
    int rem = (int)(idx - (long)which * 128 * KDIM);
    int m = rem / KDIM, k = rem - m * KDIM;
    int tap = k >> 8, ci = k & 255;
    float v = 0.f;
    if (which == 0) {
        if (m < 80)       v = logits_w[(m * 256 + ci) * 9 + tap];
        else if (m == 80) v = ctr_w[ci * 9 + tap];
    } else {
        if (m < 4) v = reg_w[(m * 256 + ci) * 9 + tap];
    }
    g_Wh[idx] = __float2half(v);
    if (k == 0) {
        float bv = 0.f;
        if (which == 0) { if (m < 80) bv = logits_b[m]; else if (m == 80) bv = ctr_b[0]; }
        else            { if (m < 4)  bv = reg_b[m]; }
        g_hb[which * 128 + m] = bv;
    }
}

// Interior: NCHW f32 feat -> padded NHWC fp16 (Xin). Tail: zero borders of 5.
__global__ void prep_act_kernel(const float* __restrict__ feat, int H, int W)
{
    const int HW = H * W;
    const int NP = BATCH * HW;
    const int Hp = H + 2, Wp = W + 2;
    const long nInt = (long)NP * 32;
    const int cnt = 2 * Wp + 2 * H;
    const long nBor = (long)BATCH * cnt * 32;
    long idx = (long)blockIdx.x * blockDim.x + threadIdx.x;
    if (idx < nInt) {
        int g = (int)(idx / NP);
        int p = (int)(idx - (long)g * NP);
        int b = p / HW, hw = p - b * HW;
        int y = hw / W, x = hw - y * W;
        const float* src = feat + ((long)b * 256 + g * 8) * HW + hw;
        __half hh[8];
#pragma unroll
        for (int i = 0; i < 8; i++) hh[i] = __float2half(src[(long)i * HW]);
        long a = (((long)b * Hp + y + 1) * Wp + x + 1) * 256 + g * 8;
        *(uint4*)(g_Xin + a) = *(const uint4*)hh;
        return;
    }
    idx -= nInt;
    if (idx >= 5 * nBor) return;
    int buf = (int)(idx / nBor);
    long r0 = idx - (long)buf * nBor;
    int b = (int)(r0 / (cnt * 32));
    int r = (int)(r0 - (long)b * cnt * 32);
    int i = r >> 5, q = r & 31;
    int y, x;
    if (i < Wp)              { y = 0;      x = i; }
    else if (i < 2 * Wp)     { y = Hp - 1; x = i - Wp; }
    else if (i < 2 * Wp + H) { y = 1 + (i - 2 * Wp);     x = 0; }
    else                     { y = 1 + (i - 2 * Wp - H); x = Wp - 1; }
    long a = (((long)b * Hp + y) * Wp + x) * 256 + q * 8;
    __half* dst = (buf == 0) ? g_Xin : (buf == 1) ? g_Xa1 : (buf == 2) ? g_Xb1
                 : (buf == 3) ? g_Xa2 : g_Xb2;
    *(uint4*)(dst + a) = make_uint4(0, 0, 0, 0);
}

// ---------------- conv via mma.sync ----------------------------------------
// Stage = K64: 4 tiles {W_e, W_o, X_e, X_o} of [128 rows][32 halfs], row
// stride 80 B (conflict-free). Double buffer; race-free order:
// CP_WAIT(0) -> sync -> issue(next) -> compute.
#define ROWB 80
#define TILE_BYTES (128 * ROWB)          // 10240
#define STAGE_B (4 * TILE_BYTES)         // 40960
#define DYN_SMEM (2 * STAGE_B + 512 + 64)

__global__ __launch_bounds__(256, 2) void conv_mma_kernel(
    const __half* __restrict__ Wt, long wstride,
    const float* __restrict__ bias, const float* __restrict__ bias2,
    const __half* __restrict__ Xp, const __half* __restrict__ Xp2,
    __half* __restrict__ convout, float* __restrict__ dout,
    const float* __restrict__ scales, int lvl,
    int H, int W, int mode, long out_boff, long lvl_off)
{
    const int Hp = H + 2, Wp = W + 2, HW = H * W;
    const int N = BATCH * HW;
    const int n0 = blockIdx.x * 128;
    const int by = blockIdx.y;
    int tower, m0, emode, Meff;
    if (mode == 0) { tower = by >> 1; m0 = (by & 1) * 128; emode = 0; Meff = 128; }
    else           { tower = by; m0 = 0; emode = tower ? 2 : 1; Meff = tower ? 4 : 85; }
    const __half* Wb = Wt + (long)tower * wstride;
    const __half* Xs = tower ? Xp2 : Xp;
    const float* biasP = tower ? bias2 : bias;

    const int tid = threadIdx.x, wid = tid >> 5, lid = tid & 31;

    extern __shared__ char dsm[];
    const uint32_t sb0 = smem_to_u32(dsm);
    int* sbase = (int*)(dsm + 2 * STAGE_B);

    if (tid < 128) {
        int p = n0 + tid;
        if (p >= N) p = N - 1;
        int b = p / HW, hw = p - b * HW;
        int y = hw / W, x = hw - y * W;
        sbase[tid] = ((b * Hp + y) * Wp + x) * 256;
    }
    __syncthreads();

    // 8 cp.async channels (16B each) per stage.
    const __half* gbase[8];
    uint32_t sdst[8];
    bool isA[8];
    int ksub[8];
#pragma unroll
    for (int c = 0; c < 8; c++) {
        int id = c * 256 + tid;        // 0..2047
        int tile = id >> 9;            // 0:W_e 1:W_o 2:X_e 3:X_o
        int e = id & 511;
        int row = e >> 2, c4 = e & 3;
        isA[c] = (tile < 2);
        ksub[c] = tile & 1;
        if (tile < 2) gbase[c] = Wb + (long)(m0 + row) * KDIM + c4 * 8;
        else          gbase[c] = Xs + (long)sbase[row] + c4 * 8;
        sdst[c] = sb0 + tile * TILE_BYTES + row * ROWB + c4 * 16;
    }

    const int NST = KDIM / 64;         // 36
    const int wm = wid & 3, wn = wid >> 2;
    const bool um0 = (wm * 32) < Meff;
    const bool um1 = (wm * 32 + 16) < Meff;

    float acc[2][8][4];
#pragma unroll
    for (int i = 0; i < 2; i++)
#pragma unroll
        for (int j = 0; j < 8; j++)
#pragma unroll
            for (int k = 0; k < 4; k++) acc[i][j][k] = 0.f;

    auto issue = [&](int ss) {
        const uint32_t boff = (uint32_t)(ss & 1) * STAGE_B;
#pragma unroll
        for (int c = 0; c < 8; c++) {
            const int kc = 2 * ss + ksub[c];
            long off;
            if (isA[c]) off = kc * 32;
            else {
                const int tap = kc >> 3;
                off = ((tap / 3) * Wp + (tap % 3)) * 256 + (kc & 7) * 32;
            }
            CP_ASYNC16(sdst[c] + boff, gbase[c] + off);
        }
        CP_COMMIT();
    };

    issue(0);
    for (int ss = 0; ss < NST; ss++) {
        CP_WAIT0();
        __syncthreads();
        if (ss + 1 < NST) issue(ss + 1);

        const uint32_t tb = sb0 + (uint32_t)(ss & 1) * STAGE_B;
#pragma unroll
        for (int sub = 0; sub < 2; sub++) {
            const uint32_t Ab = tb + sub * TILE_BYTES;
            const uint32_t Bb = tb + (2 + sub) * TILE_BYTES;
#pragma unroll
            for (int sl = 0; sl < 2; sl++) {
                uint32_t ah[2][4];
                if (um0) {
                    uint32_t ao = (uint32_t)((wm * 32 + (lid & 15)) * ROWB
                                             + (sl * 16 + (lid >> 4) * 8) * 2);
                    ldsm4(ah[0], Ab + ao);
                }
                if (um1) {
                    uint32_t ao = (uint32_t)((wm * 32 + 16 + (lid & 15)) * ROWB
                                             + (sl * 16 + (lid >> 4) * 8) * 2);
                    ldsm4(ah[1], Ab + ao);
                }
#pragma unroll
                for (int ng = 0; ng < 4; ng++) {
                    const int q = lid >> 3;
                    uint32_t bo = (uint32_t)((wn * 64 + ng * 16 + (q >> 1) * 8 + (lid & 7)) * ROWB
                                             + (sl * 16 + (q & 1) * 8) * 2);
                    uint32_t bh[4];
                    ldsm4(bh, Bb + bo);
                    if (um0) {
#pragma unroll
                        for (int h = 0; h < 2; h++)
                            mma16816(acc[0][ng * 2 + h], ah[0], &bh[h * 2]);
                    }
                    if (um1) {
#pragma unroll
                        for (int h = 0; h < 2; h++)
                            mma16816(acc[1][ng * 2 + h], ah[1], &bh[h * 2]);
                    }
                }
            }
        }
    }
    __syncthreads();   // all warps done with smem before sred reuse

    // ---------------- epilogue ----------------
    const float sc = (emode == 2) ? scales[lvl] : 0.f;
    const int b0 = n0 / HW;
    float* sred = (float*)dsm;           // 96 floats: s[48], s2[48]
    float ts[12], ts2[12];
    if (emode == 0) {
        if (tid < 96) sred[tid] = 0.f;
#pragma unroll
        for (int i = 0; i < 12; i++) { ts[i] = 0.f; ts2[i] = 0.f; }
        __syncthreads();
    }
    __half* cvo = convout + (size_t)tower * CONVOFF;

#pragma unroll
    for (int mi = 0; mi < 2; mi++) {
        if (!(mi == 0 ? um0 : um1)) continue;
        const int mlo = m0 + wm * 32 + mi * 16 + (lid >> 2);
        const float bv0 = biasP[mlo];
        const float bv1 = biasP[mlo + 8];
#pragma unroll
        for (int ng = 0; ng < 4; ng++) {
#pragma unroll
            for (int h = 0; h < 2; h++) {
                const float* d = acc[mi][ng * 2 + h];
                const int n = n0 + wn * 64 + ng * 16 + h * 8 + 2 * (lid & 3);
#pragma unroll
                for (int e = 0; e < 4; e++) {
                    const int p = n + (e & 1);
                    const int half_ = (e >> 1);
                    const int m = mlo + half_ * 8;
                    if (p >= N) continue;
                    float v = d[e] + (half_ ? bv1 : bv0);
                    if (emode == 0) {
                        cvo[(size_t)p * 256 + m] = __float2half(v);
                        int db = p / HW - b0;
                        int si = (mi * 2 + half_) * 3 + db;
                        ts[si] += v; ts2[si] += v * v;
                    } else {
                        int b = p / HW, hw = p - b * HW;
                        long ob = (long)b * out_boff + lvl_off;
                        if (emode == 1) {
                            if (m < 80)       dout[ob + (long)m * HW + hw] = v;
                            else if (m == 80) dout[ob + 84L * HW + hw] = v;
                        } else {
                            if (m < 4) dout[ob + (long)(80 + m) * HW + hw] = expf(sc * v);
                        }
                    }
                }
            }
        }
    }

    if (emode == 0) {
#pragma unroll
        for (int i = 0; i < 12; i++) {
            if (ts[i] == 0.f && ts2[i] == 0.f) continue;
            int db = i % 3, q = i / 3;
            int half_ = q & 1, mi = q >> 1;
            int gl = wm * 4 + mi * 2 + half_;
            atomicAdd(&sred[db * 16 + gl], ts[i]);
            atomicAdd(&sred[48 + db * 16 + gl], ts2[i]);
        }
        __syncthreads();
        if (tid < 48) {
            int db = tid >> 4, gl = tid & 15;
            int b = b0 + db;
            if (b < BATCH) {
                int g = (m0 >> 3) + gl;
                int bg = tower * 256 + b * 32 + g;
                g_psA [(size_t)bg * PSMAX + blockIdx.x] = sred[tid];
                g_ps2A[(size_t)bg * PSMAX + blockIdx.x] = sred[48 + tid];
            }
        }
    }
}

// ---------------- GroupNorm stage 2 + apply ---------------------------------
__global__ __launch_bounds__(256) void gn_stats2_kernel(int HW, int nblk)
{
    const int bg = blockIdx.x;          // 0..511 (tower*256 + b*32 + g)
    const int b = (bg >> 5) & 7;
    const int N = BATCH * HW;
    float s = 0.f, s2 = 0.f;
    for (int nb = threadIdx.x; nb < nblk; nb += 256) {
        int p0 = nb * 128;
        int bfirst = p0 / HW;
        int pl = p0 + 127; if (pl >= N) pl = N - 1;
        int blast = pl / HW;
        if (b >= bfirst && b <= blast) {
            s  += g_psA [(size_t)bg * PSMAX + nb];
            s2 += g_ps2A[(size_t)bg * PSMAX + nb];
        }
    }
    __shared__ float ss[256], ss2[256];
    ss[threadIdx.x] = s; ss2[threadIdx.x] = s2;
    __syncthreads();
    for (int o = 128; o > 0; o >>= 1) {
        if (threadIdx.x < o) {
            ss[threadIdx.x]  += ss[threadIdx.x + o];
            ss2[threadIdx.x] += ss2[threadIdx.x + o];
        }
        __syncthreads();
    }
    if (threadIdx.x == 0) {
        float cnt = 8.f * HW;
        float mean = ss[0] / cnt;
        float var  = ss2[0] / cnt - mean * mean;
        g_mean[bg] = mean;
        g_rstd[bg] = rsqrtf(var + 1e-5f);
    }
}

// Fused GN apply + ReLU for both towers.
__global__ __launch_bounds__(256) void gn_apply_kernel(
    const __half* __restrict__ co,
    __half* __restrict__ dstC, __half* __restrict__ dstB,
    const float* __restrict__ gammaC, const float* __restrict__ betaC,
    const float* __restrict__ gammaB, const float* __restrict__ betaB,
    int H, int W)
{
    const int HW = H * W;
    const long NT = (long)BATCH * HW * 32;
    long idx = (long)blockIdx.x * blockDim.x + threadIdx.x;
    if (idx >= 2 * NT) return;
    const int tower = (idx >= NT);
    if (tower) idx -= NT;
    int g = (int)(idx & 31);
    int p = (int)(idx >> 5);
    int b = p / HW, hw = p - b * HW;
    int y = hw / W, x = hw - y * W;
    const int bg = tower * 256 + b * 32 + g;
    const float mean = g_mean[bg], rstd = g_rstd[bg];
    const float* gamma = tower ? gammaB : gammaC;
    const float* beta  = tower ? betaB  : betaC;
    const __half* src = co + (size_t)tower * CONVOFF + (size_t)p * 256 + g * 8;
    uint4 raw = __ldcs((const uint4*)src);
    const __half* hv = (const __half*)&raw;
    __half hh[8];
#pragma unroll
    for (int i = 0; i < 8; i++) {
        int c = g * 8 + i;
        float v = (__half2float(hv[i]) - mean) * rstd * gamma[c] + beta[c];
        hh[i] = __float2half(v > 0.f ? v : 0.f);
    }
    long a = (((long)b * (H + 2) + y + 1) * (W + 2) + x + 1) * 256 + g * 8;
    __half* dst = tower ? dstB : dstC;
    *(uint4*)(dst + a) = *(const uint4*)hh;
}

// All-level FCOS locations in one launch.
__global__ __launch_bounds__(256) void loc_all_kernel(float* __restrict__ out, long base)
{
    static const int WS[5]  = {152, 76, 38, 19, 10};
    static const int STR[5] = {8, 16, 32, 64, 128};
    static const int OFF[5] = {0, 15200, 19000, 19950, 20197};
    int idx = blockIdx.x * blockDim.x + threadIdx.x;
    if (idx >= 20267) return;
    int l = 4;
    if (idx < 15200) l = 0;
    else if (idx < 19000) l = 1;
    else if (idx < 19950) l = 2;
    else if (idx < 20197) l = 3;
    int r = idx - OFF[l];
    int y = r / WS[l], x = r - y * WS[l];
    out[base + 2 * idx]     = (float)(x * STR[l] + STR[l] / 2);
    out[base + 2 * idx + 1] = (float)(y * STR[l] + STR[l] / 2);
}

// ---------------------------------------------------------------------------
extern "C" void kernel_launch(void* const* d_in, const int* in_sizes, int n_in,
                              void* d_out, int out_size)
{
    (void)in_sizes; (void)n_in; (void)out_size;
    const float* feats[5];
    for (int i = 0; i < 5; i++) feats[i] = (const float*)d_in[i];
    const float* cls_w    = (const float*)d_in[5];
    const float* cls_b    = (const float*)d_in[6];
    const float* cls_gn_g = (const float*)d_in[7];
    const float* cls_gn_b = (const float*)d_in[8];
    const float* box_w    = (const float*)d_in[9];
    const float* box_b    = (const float*)d_in[10];
    const float* box_gn_g = (const float*)d_in[11];
    const float* box_gn_b = (const float*)d_in[12];
    const float* logits_w = (const float*)d_in[13];
    const float* logits_b = (const float*)d_in[14];
    const float* ctr_w    = (const float*)d_in[15];
    const float* ctr_b    = (const float*)d_in[16];
    const float* reg_w    = (const float*)d_in[17];
    const float* reg_b    = (const float*)d_in[18];
    const float* scales   = (const float*)d_in[19];
    float* out = (float*)d_out;

    cudaFuncSetAttribute(conv_mma_kernel,
                         cudaFuncAttributeMaxDynamicSharedMemorySize, DYN_SMEM);

    __half *Xin, *Xa1, *Xb1, *Xa2, *Xb2, *Wt, *Wh, *convout;
    float *hb;
    cudaGetSymbolAddress((void**)&Xin, g_Xin);
    cudaGetSymbolAddress((void**)&Xa1, g_Xa1);
    cudaGetSymbolAddress((void**)&Xb1, g_Xb1);
    cudaGetSymbolAddress((void**)&Xa2, g_Xa2);
    cudaGetSymbolAddress((void**)&Xb2, g_Xb2);
    cudaGetSymbolAddress((void**)&Wt, g_Wt);
    cudaGetSymbolAddress((void**)&Wh, g_Wh);
    cudaGetSymbolAddress((void**)&convout, g_convout);
    cudaGetSymbolAddress((void**)&hb, g_hb);

    static const int HS[5]  = {100, 50, 25, 13, 7};
    static const int WS[5]  = {152, 76, 38, 19, 10};

    long out_boff = 0;
    for (int l = 0; l < 5; l++) out_boff += 85L * HS[l] * WS[l];
    const long locs_base = (long)BATCH * out_boff;

    prep_weights_kernel<<<(int)((8L * 256 * KDIM + 255) / 256), 256>>>(cls_w, box_w);
    prep_heads_kernel<<<(int)((2L * 128 * KDIM + 255) / 256), 256>>>(
        logits_w, logits_b, ctr_w, ctr_b, reg_w, reg_b);

    long lvl_off = 0;
    for (int l = 0; l < 5; l++) {
        const int H = HS[l], W = WS[l], HW = H * W;
        const int N = BATCH * HW;
        const int nblk = (N + 127) / 128;
        const int Hp = H + 2, Wp = W + 2;
        const int cnt = 2 * Wp + 2 * H;
        const long pa_tot = (long)N * 32 + 5L * BATCH * cnt * 32;
        const int pg = (int)((pa_tot + 255) / 256);
        const int ag = (int)((2L * N * 32 + 255) / 256);

        prep_act_kernel<<<pg, 256>>>(feats[l], H, W);

        __half* srcC[4] = {Xin, Xa1, Xb1, Xa1};
        __half* dstC[4] = {Xa1, Xb1, Xa1, Xb1};
        __half* srcB[4] = {Xin, Xa2, Xb2, Xa2};
        __half* dstB[4] = {Xa2, Xb2, Xa2, Xb2};

        dim3 gconv(nblk, 4);   // 2 m-tiles x 2 towers
        dim3 ghead(nblk, 2);   // 2 towers

        for (int i = 0; i < 4; i++) {
            conv_mma_kernel<<<gconv, 256, DYN_SMEM>>>(
                Wt + (long)i * 256 * KDIM, 4L * 256 * KDIM,
                cls_b + i * 256, box_b + i * 256,
                srcC[i], srcB[i], convout, nullptr,
                scales, l, H, W, 0, 0, 0);
            gn_stats2_kernel<<<512, 256>>>(HW, nblk);
            gn_apply_kernel<<<ag, 256>>>(convout, dstC[i], dstB[i],
                                         cls_gn_g + i * 256, cls_gn_b + i * 256,
                                         box_gn_g + i * 256, box_gn_b + i * 256,
                                         H, W);
        }
        conv_mma_kernel<<<ghead, 256, DYN_SMEM>>>(
            Wh, 128L * KDIM, hb, hb + 128,
            Xb1, Xb2, nullptr, out,
            scales, l, H, W, 3, out_boff, lvl_off);

        lvl_off += 85L * HW;
    }
    loc_all_kernel<<<(20267 + 255) / 256, 256>>>(out, locs_base);
}

// round 15
// speedup vs baseline: 2.4264x; 1.1286x over previous
#include <cuda_runtime.h>
#include <cuda_fp16.h>
#include <math.h>
#include <stdint.h>

// ===========================================================================
// FCOS head via mma.sync fp16 tensor cores (compute_100-safe; no tcgen05).
// Conv3x3 as implicit GEMM, plain fp16 W and X. R15 (= R14 + BOR_TOTAL fix):
// ALL 5 FPN levels fused into each launch (level decoded from blockIdx.x via
// constant tables). 17 launches total. K=64 stages, race-free double buffer,
// towers fused (grid y=4), fp16 convout, fused GN stats/apply, fused heads.
// ===========================================================================

#define BATCH 8
#define KDIM 2304
#define PSMAX 950
#define TOTPAD 170136L            // sum of padded positions over levels
#define TOTPOS 162136L            // sum of positions over levels
#define CONVOFF (TOTPOS * 256)
#define OUTBOFF 1722695L

// Per-level constant tables.
__device__ __constant__ int  c_H[5]    = {100, 50, 25, 13, 7};
__device__ __constant__ int  c_W[5]    = {152, 76, 38, 19, 10};
__device__ __constant__ int  c_HW[5]   = {15200, 3800, 950, 247, 70};
__device__ __constant__ int  c_N[5]    = {121600, 30400, 7600, 1976, 560};
__device__ __constant__ int  c_NBLK[5] = {950, 238, 60, 16, 5};
__device__ __constant__ int  c_BCUM[5] = {950, 1188, 1248, 1264, 1269};
__device__ __constant__ long c_XB[5]   = {0, 125664, 158112, 166752, 169272};
__device__ __constant__ long c_CB[5]   = {0, 121600, 152000, 159600, 161576};
__device__ __constant__ long c_LOFF[5] = {0, 1292000, 1615000, 1695750, 1716745};

// ---------------- device buffers -------------------------------------------
__device__ __align__(16) __half g_Xin[TOTPAD * 256];
__device__ __align__(16) __half g_Xa1[TOTPAD * 256];
__device__ __align__(16) __half g_Xb1[TOTPAD * 256];
__device__ __align__(16) __half g_Xa2[TOTPAD * 256];
__device__ __align__(16) __half g_Xb2[TOTPAD * 256];
__device__ __align__(16) __half g_convout[2 * CONVOFF];
__device__ __align__(16) __half g_Wt[8 * 256 * KDIM];
__device__ __align__(16) __half g_Wh[2 * 128 * KDIM];
__device__ float g_hb[2 * 128];
__device__ float g_psA [2560L * PSMAX];
__device__ float g_ps2A[2560L * PSMAX];
__device__ float g_mean[2560];
__device__ float g_rstd[2560];

// ---------------- PTX helpers ----------------------------------------------
__device__ __forceinline__ uint32_t smem_to_u32(const void* p) {
    uint32_t a;
    asm("{ .reg .u64 t; cvta.to.shared.u64 t, %1; cvt.u32.u64 %0, t; }"
        : "=r"(a) : "l"(p));
    return a;
}
#define CP_ASYNC16(dst, src) \
    asm volatile("cp.async.cg.shared.global [%0], [%1], 16;" \
                 :: "r"(dst), "l"(src))
#define CP_COMMIT() asm volatile("cp.async.commit_group;" ::: "memory")
#define CP_WAIT0()  asm volatile("cp.async.wait_group 0;" ::: "memory")

__device__ __forceinline__ void ldsm4(uint32_t (&r)[4], uint32_t a) {
    asm volatile("ldmatrix.sync.aligned.m8n8.x4.shared.b16 {%0,%1,%2,%3}, [%4];"
        : "=r"(r[0]), "=r"(r[1]), "=r"(r[2]), "=r"(r[3]) : "r"(a));
}
__device__ __forceinline__ void mma16816(float* d, const uint32_t* a, const uint32_t* b) {
    asm volatile(
        "mma.sync.aligned.m16n8k16.row.col.f32.f16.f16.f32 "
        "{%0,%1,%2,%3}, {%4,%5,%6,%7}, {%8,%9}, {%0,%1,%2,%3};"
        : "+f"(d[0]), "+f"(d[1]), "+f"(d[2]), "+f"(d[3])
        : "r"(a[0]), "r"(a[1]), "r"(a[2]), "r"(a[3]), "r"(b[0]), "r"(b[1]));
}

__device__ __forceinline__ int lvl_of_block(int bx) {
    return (bx < c_BCUM[0]) ? 0 : (bx < c_BCUM[1]) ? 1
         : (bx < c_BCUM[2]) ? 2 : (bx < c_BCUM[3]) ? 3 : 4;
}

// ---------------- prep kernels ---------------------------------------------
__global__ void prep_weights_kernel(const float* __restrict__ cls_w,
                                    const float* __restrict__ box_w)
{
    long idx = (long)blockIdx.x * blockDim.x + threadIdx.x;
    if (idx >= 8L * 256 * KDIM) return;
    int j = (int)(idx / (256 * KDIM));
    int rem = (int)(idx - (long)j * 256 * KDIM);
    int m = rem / KDIM, k = rem - m * KDIM;
    int tap = k >> 8, ci = k & 255;
    const float* src = (j < 4) ? cls_w + (long)j * 256 * KDIM
                               : box_w + (long)(j - 4) * 256 * KDIM;
    g_Wt[idx] = __float2half(src[(m * 256 + ci) * 9 + tap]);
}

__global__ void prep_heads_kernel(const float* __restrict__ logits_w,
                                  const float* __restrict__ logits_b,
                                  const float* __restrict__ ctr_w,
                                  const float* __restrict__ ctr_b,
                                  const float* __restrict__ reg_w,
                                  const float* __restrict__ reg_b)
{
    long idx = (long)blockIdx.x * blockDim.x + threadIdx.x;
    if (idx >= 2L * 128 * KDIM) return;
    int which = (int)(idx / (128 * KDIM));
    int rem = (int)(idx - (long)which * 128 * KDIM);
    int m = rem / KDIM, k = rem - m * KDIM;
    int tap = k >> 8, ci = k & 255;
    float v = 0.f;
    if (which == 0) {
        if (m < 80)       v = logits_w[(m * 256 + ci) * 9 + tap];
        else if (m == 80) v = ctr_w[ci * 9 + tap];
    } else {
        if (m < 4) v = reg_w[(m * 256 + ci) * 9 + tap];
    }
    g_Wh[idx] = __float2half(v);
    if (k == 0) {
        float bv = 0.f;
        if (which == 0) { if (m < 80) bv = logits_b[m]; else if (m == 80) bv = ctr_b[0]; }
        else            { if (m < 4)  bv = reg_b[m]; }
        g_hb[which * 128 + m] = bv;
    }
}

// All levels: interior NCHW f32 -> padded NHWC fp16 (Xin); borders of 5 bufs.
__device__ __constant__ long c_ICUM[5] = {3891200, 4864000, 5107200, 5170432, 5188352};
__device__ __constant__ int  c_LBOR[5] = {130048, 195584, 228864, 246272, 256000};
#define BOR_TOTAL 256000L         // per-buffer border elements over all levels

__global__ void prep_act_kernel(const float* __restrict__ f0,
                                const float* __restrict__ f1,
                                const float* __restrict__ f2,
                                const float* __restrict__ f3,
                                const float* __restrict__ f4)
{
    long idx = (long)blockIdx.x * blockDim.x + threadIdx.x;
    if (idx < c_ICUM[4]) {
        int l = (idx < c_ICUM[0]) ? 0 : (idx < c_ICUM[1]) ? 1
              : (idx < c_ICUM[2]) ? 2 : (idx < c_ICUM[3]) ? 3 : 4;
        long r = idx - (l ? c_ICUM[l - 1] : 0);
        const int HW = c_HW[l], W = c_W[l], Wp = W + 2, Hp = c_H[l] + 2;
        const int NP = c_N[l];
        int g = (int)(r / NP);
        int p = (int)(r - (long)g * NP);
        int b = p / HW, hw = p - b * HW;
        int y = hw / W, x = hw - y * W;
        const float* feat = (l == 0) ? f0 : (l == 1) ? f1 : (l == 2) ? f2
                          : (l == 3) ? f3 : f4;
        const float* src = feat + ((long)b * 256 + g * 8) * HW + hw;
        __half hh[8];
#pragma unroll
        for (int i = 0; i < 8; i++) hh[i] = __float2half(src[(long)i * HW]);
        long a = (c_XB[l] + (long)(b * Hp + y + 1) * Wp + x + 1) * 256 + g * 8;
        *(uint4*)(g_Xin + a) = *(const uint4*)hh;
        return;
    }
    idx -= c_ICUM[4];
    if (idx >= 5 * BOR_TOTAL) return;
    int buf = (int)(idx / BOR_TOTAL);
    int rb = (int)(idx - (long)buf * BOR_TOTAL);
    int l = (rb < c_LBOR[0]) ? 0 : (rb < c_LBOR[1]) ? 1
          : (rb < c_LBOR[2]) ? 2 : (rb < c_LBOR[3]) ? 3 : 4;
    int r0 = rb - (l ? c_LBOR[l - 1] : 0);
    const int H = c_H[l], W = c_W[l], Hp = H + 2, Wp = W + 2;
    const int cnt = 2 * Wp + 2 * H;
    int b = r0 / (cnt * 32);
    int r = r0 - b * cnt * 32;
    int i = r >> 5, q = r & 31;
    int y, x;
    if (i < Wp)              { y = 0;      x = i; }
    else if (i < 2 * Wp)     { y = Hp - 1; x = i - Wp; }
    else if (i < 2 * Wp + H) { y = 1 + (i - 2 * Wp);     x = 0; }
    else                     { y = 1 + (i - 2 * Wp - H); x = Wp - 1; }
    long a = (c_XB[l] + (long)(b * Hp + y) * Wp + x) * 256 + q * 8;
    __half* dst = (buf == 0) ? g_Xin : (buf == 1) ? g_Xa1 : (buf == 2) ? g_Xb1
                 : (buf == 3) ? g_Xa2 : g_Xb2;
    *(uint4*)(dst + a) = make_uint4(0, 0, 0, 0);
}

// ---------------- conv via mma.sync (all levels fused) ----------------------
#define ROWB 80
#define TILE_BYTES (128 * ROWB)
#define STAGE_B (4 * TILE_BYTES)
#define DYN_SMEM (2 * STAGE_B + 512 + 64)

__global__ __launch_bounds__(256, 2) void conv_mma_kernel(
    const __half* __restrict__ Wt, long wstride,
    const float* __restrict__ bias, const float* __restrict__ bias2,
    const __half* __restrict__ Xp, const __half* __restrict__ Xp2,
    __half* __restrict__ convout, float* __restrict__ dout,
    const float* __restrict__ scales, int mode)
{
    const int bx = blockIdx.x;
    const int l = lvl_of_block(bx);
    const int lb = bx - (l ? c_BCUM[l - 1] : 0);
    const int H = c_H[l], W = c_W[l], HW = c_HW[l], N = c_N[l];
    const int Hp = H + 2, Wp = W + 2;
    const int n0 = lb * 128;
    const int by = blockIdx.y;
    int tower, m0, emode, Meff;
    if (mode == 0) { tower = by >> 1; m0 = (by & 1) * 128; emode = 0; Meff = 128; }
    else           { tower = by; m0 = 0; emode = tower ? 2 : 1; Meff = tower ? 4 : 85; }
    const __half* Wb = Wt + (long)tower * wstride;
    const __half* Xs = (tower ? Xp2 : Xp) + c_XB[l] * 256;
    const float* biasP = tower ? bias2 : bias;

    const int tid = threadIdx.x, wid = tid >> 5, lid = tid & 31;

    extern __shared__ char dsm[];
    const uint32_t sb0 = smem_to_u32(dsm);
    int* sbase = (int*)(dsm + 2 * STAGE_B);

    if (tid < 128) {
        int p = n0 + tid;
        if (p >= N) p = N - 1;
        int b = p / HW, hw = p - b * HW;
        int y = hw / W, x = hw - y * W;
        sbase[tid] = ((b * Hp + y) * Wp + x) * 256;
    }
    __syncthreads();

    const __half* gbase[8];
    uint32_t sdst[8];
    bool isA[8];
    int ksub[8];
#pragma unroll
    for (int c = 0; c < 8; c++) {
        int id = c * 256 + tid;
        int tile = id >> 9;            // 0:W_e 1:W_o 2:X_e 3:X_o
        int e = id & 511;
        int row = e >> 2, c4 = e & 3;
        isA[c] = (tile < 2);
        ksub[c] = tile & 1;
        if (tile < 2) gbase[c] = Wb + (long)(m0 + row) * KDIM + c4 * 8;
        else          gbase[c] = Xs + (long)sbase[row] + c4 * 8;
        sdst[c] = sb0 + tile * TILE_BYTES + row * ROWB + c4 * 16;
    }

    const int NST = KDIM / 64;
    const int wm = wid & 3, wn = wid >> 2;
    const bool um0 = (wm * 32) < Meff;
    const bool um1 = (wm * 32 + 16) < Meff;

    float acc[2][8][4];
#pragma unroll
    for (int i = 0; i < 2; i++)
#pragma unroll
        for (int j = 0; j < 8; j++)
#pragma unroll
            for (int k = 0; k < 4; k++) acc[i][j][k] = 0.f;

    auto issue = [&](int ss) {
        const uint32_t boff = (uint32_t)(ss & 1) * STAGE_B;
#pragma unroll
        for (int c = 0; c < 8; c++) {
            const int kc = 2 * ss + ksub[c];
            long off;
            if (isA[c]) off = kc * 32;
            else {
                const int tap = kc >> 3;
                off = ((tap / 3) * Wp + (tap % 3)) * 256 + (kc & 7) * 32;
            }
            CP_ASYNC16(sdst[c] + boff, gbase[c] + off);
        }
        CP_COMMIT();
    };

    issue(0);
    for (int ss = 0; ss < NST; ss++) {
        CP_WAIT0();
        __syncthreads();
        if (ss + 1 < NST) issue(ss + 1);

        const uint32_t tb = sb0 + (uint32_t)(ss & 1) * STAGE_B;
#pragma unroll
        for (int sub = 0; sub < 2; sub++) {
            const uint32_t Ab = tb + sub * TILE_BYTES;
            const uint32_t Bb = tb + (2 + sub) * TILE_BYTES;
#pragma unroll
            for (int sl = 0; sl < 2; sl++) {
                uint32_t ah[2][4];
                if (um0) {
                    uint32_t ao = (uint32_t)((wm * 32 + (lid & 15)) * ROWB
                                             + (sl * 16 + (lid >> 4) * 8) * 2);
                    ldsm4(ah[0], Ab + ao);
                }
                if (um1) {
                    uint32_t ao = (uint32_t)((wm * 32 + 16 + (lid & 15)) * ROWB
                                             + (sl * 16 + (lid >> 4) * 8) * 2);
                    ldsm4(ah[1], Ab + ao);
                }
#pragma unroll
                for (int ng = 0; ng < 4; ng++) {
                    const int q = lid >> 3;
                    uint32_t bo = (uint32_t)((wn * 64 + ng * 16 + (q >> 1) * 8 + (lid & 7)) * ROWB
                                             + (sl * 16 + (q & 1) * 8) * 2);
                    uint32_t bh[4];
                    ldsm4(bh, Bb + bo);
                    if (um0) {
#pragma unroll
                        for (int h = 0; h < 2; h++)
                            mma16816(acc[0][ng * 2 + h], ah[0], &bh[h * 2]);
                    }
                    if (um1) {
#pragma unroll
                        for (int h = 0; h < 2; h++)
                            mma16816(acc[1][ng * 2 + h], ah[1], &bh[h * 2]);
                    }
                }
            }
        }
    }
    __syncthreads();

    // ---------------- epilogue ----------------
    const float sc = (emode == 2) ? scales[l] : 0.f;
    const int b0 = n0 / HW;
    float* sred = (float*)dsm;
    float ts[12], ts2[12];
    if (emode == 0) {
        if (tid < 96) sred[tid] = 0.f;
#pragma unroll
        for (int i = 0; i < 12; i++) { ts[i] = 0.f; ts2[i] = 0.f; }
        __syncthreads();
    }
    __half* cvo = convout + (size_t)tower * CONVOFF;

#pragma unroll
    for (int mi = 0; mi < 2; mi++) {
        if (!(mi == 0 ? um0 : um1)) continue;
        const int mlo = m0 + wm * 32 + mi * 16 + (lid >> 2);
        const float bv0 = biasP[mlo];
        const float bv1 = biasP[mlo + 8];
#pragma unroll
        for (int ng = 0; ng < 4; ng++) {
#pragma unroll
            for (int h = 0; h < 2; h++) {
                const float* d = acc[mi][ng * 2 + h];
                const int n = n0 + wn * 64 + ng * 16 + h * 8 + 2 * (lid & 3);
#pragma unroll
                for (int e = 0; e < 4; e++) {
                    const int p = n + (e & 1);
                    const int half_ = (e >> 1);
                    const int m = mlo + half_ * 8;
                    if (p >= N) continue;
                    float v = d[e] + (half_ ? bv1 : bv0);
                    if (emode == 0) {
                        cvo[(c_CB[l] + p) * 256 + m] = __float2half(v);
                        int db = p / HW - b0;
                        int si = (mi * 2 + half_) * 3 + db;
                        ts[si] += v; ts2[si] += v * v;
                    } else {
                        int b = p / HW, hw = p - b * HW;
                        long ob = (long)b * OUTBOFF + c_LOFF[l];
                        if (emode == 1) {
                            if (m < 80)       dout[ob + (long)m * HW + hw] = v;
                            else if (m == 80) dout[ob + 84L * HW + hw] = v;
                        } else {
                            if (m < 4) dout[ob + (long)(80 + m) * HW + hw] = expf(sc * v);
                        }
                    }
                }
            }
        }
    }

    if (emode == 0) {
#pragma unroll
        for (int i = 0; i < 12; i++) {
            if (ts[i] == 0.f && ts2[i] == 0.f) continue;
            int db = i % 3, q = i / 3;
            int half_ = q & 1, mi = q >> 1;
            int gl = wm * 4 + mi * 2 + half_;
            atomicAdd(&sred[db * 16 + gl], ts[i]);
            atomicAdd(&sred[48 + db * 16 + gl], ts2[i]);
        }
        __syncthreads();
        if (tid < 48) {
            int db = tid >> 4, gl = tid & 15;
            int b = b0 + db;
            if (b < BATCH) {
                int g = (m0 >> 3) + gl;
                long bg = (long)(l * 2 + tower) * 256 + b * 32 + g;
                g_psA [bg * PSMAX + lb] = sred[tid];
                g_ps2A[bg * PSMAX + lb] = sred[48 + tid];
            }
        }
    }
}

// ---------------- GroupNorm stage 2 (all levels) -----------------------------
__global__ __launch_bounds__(256) void gn_stats2_kernel()
{
    const int bg = blockIdx.x;          // 0..2559 = l*512 + tower*256 + b*32 + g
    const int l = bg >> 9;
    const int b = (bg >> 5) & 7;
    const int HW = c_HW[l], N = c_N[l], nblk = c_NBLK[l];
    float s = 0.f, s2 = 0.f;
    for (int nb = threadIdx.x; nb < nblk; nb += 256) {
        int p0 = nb * 128;
        int bfirst = p0 / HW;
        int pl = p0 + 127; if (pl >= N) pl = N - 1;
        int blast = pl / HW;
        if (b >= bfirst && b <= blast) {
            s  += g_psA [(long)bg * PSMAX + nb];
            s2 += g_ps2A[(long)bg * PSMAX + nb];
        }
    }
    __shared__ float ss[256], ss2[256];
    ss[threadIdx.x] = s; ss2[threadIdx.x] = s2;
    __syncthreads();
    for (int o = 128; o > 0; o >>= 1) {
        if (threadIdx.x < o) {
            ss[threadIdx.x]  += ss[threadIdx.x + o];
            ss2[threadIdx.x] += ss2[threadIdx.x + o];
        }
        __syncthreads();
    }
    if (threadIdx.x == 0) {
        float cnt = 8.f * HW;
        float mean = ss[0] / cnt;
        float var  = ss2[0] / cnt - mean * mean;
        g_mean[bg] = mean;
        g_rstd[bg] = rsqrtf(var + 1e-5f);
    }
}

// GN apply + ReLU, all levels + both towers fused.
__device__ __constant__ long c_A2CUM[5] =
    {7782400, 9728000, 10214400, 10340864, 10376704};

__global__ __launch_bounds__(256) void gn_apply_kernel(
    __half* __restrict__ dstC, __half* __restrict__ dstB,
    const float* __restrict__ gammaC, const float* __restrict__ betaC,
    const float* __restrict__ gammaB, const float* __restrict__ betaB)
{
    long idx = (long)blockIdx.x * blockDim.x + threadIdx.x;
    if (idx >= c_A2CUM[4]) return;
    int l = (idx < c_A2CUM[0]) ? 0 : (idx < c_A2CUM[1]) ? 1
          : (idx < c_A2CUM[2]) ? 2 : (idx < c_A2CUM[3]) ? 3 : 4;
    long r = idx - (l ? c_A2CUM[l - 1] : 0);
    const int HW = c_HW[l], W = c_W[l], Hp = c_H[l] + 2, Wp = W + 2;
    const long NT = (long)c_N[l] * 32;
    const int tower = (r >= NT);
    if (tower) r -= NT;
    int g = (int)(r & 31);
    int p = (int)(r >> 5);
    int b = p / HW, hw = p - b * HW;
    int y = hw / W, x = hw - y * W;
    const int bg = (l * 2 + tower) * 256 + b * 32 + g;
    const float mean = g_mean[bg], rstd = g_rstd[bg];
    const float* gamma = tower ? gammaB : gammaC;
    const float* beta  = tower ? betaB  : betaC;
    const __half* src = g_convout + (size_t)tower * CONVOFF
                        + (c_CB[l] + p) * 256 + g * 8;
    uint4 raw = __ldcs((const uint4*)src);
    const __half* hv = (const __half*)&raw;
    __half hh[8];
#pragma unroll
    for (int i = 0; i < 8; i++) {
        int c = g * 8 + i;
        float v = (__half2float(hv[i]) - mean) * rstd * gamma[c] + beta[c];
        hh[i] = __float2half(v > 0.f ? v : 0.f);
    }
    long a = (c_XB[l] + (long)(b * Hp + y + 1) * Wp + x + 1) * 256 + g * 8;
    __half* dst = tower ? dstB : dstC;
    *(uint4*)(dst + a) = *(const uint4*)hh;
}

// All-level FCOS locations.
__global__ __launch_bounds__(256) void loc_all_kernel(float* __restrict__ out, long base)
{
    static const int WS_[5] = {152, 76, 38, 19, 10};
    static const int STR[5] = {8, 16, 32, 64, 128};
    static const int OFF[5] = {0, 15200, 19000, 19950, 20197};
    int idx = blockIdx.x * blockDim.x + threadIdx.x;
    if (idx >= 20267) return;
    int l = 4;
    if (idx < 15200) l = 0;
    else if (idx < 19000) l = 1;
    else if (idx < 19950) l = 2;
    else if (idx < 20197) l = 3;
    int r = idx - OFF[l];
    int y = r / WS_[l], x = r - y * WS_[l];
    out[base + 2 * idx]     = (float)(x * STR[l] + STR[l] / 2);
    out[base + 2 * idx + 1] = (float)(y * STR[l] + STR[l] / 2);
}

// ---------------------------------------------------------------------------
extern "C" void kernel_launch(void* const* d_in, const int* in_sizes, int n_in,
                              void* d_out, int out_size)
{
    (void)in_sizes; (void)n_in; (void)out_size;
    const float* feats[5];
    for (int i = 0; i < 5; i++) feats[i] = (const float*)d_in[i];
    const float* cls_w    = (const float*)d_in[5];
    const float* cls_b    = (const float*)d_in[6];
    const float* cls_gn_g = (const float*)d_in[7];
    const float* cls_gn_b = (const float*)d_in[8];
    const float* box_w    = (const float*)d_in[9];
    const float* box_b    = (const float*)d_in[10];
    const float* box_gn_g = (const float*)d_in[11];
    const float* box_gn_b = (const float*)d_in[12];
    const float* logits_w = (const float*)d_in[13];
    const float* logits_b = (const float*)d_in[14];
    const float* ctr_w    = (const float*)d_in[15];
    const float* ctr_b    = (const float*)d_in[16];
    const float* reg_w    = (const float*)d_in[17];
    const float* reg_b    = (const float*)d_in[18];
    const float* scales   = (const float*)d_in[19];
    float* out = (float*)d_out;

    cudaFuncSetAttribute(conv_mma_kernel,
                         cudaFuncAttributeMaxDynamicSharedMemorySize, DYN_SMEM);

    __half *Xin, *Xa1, *Xb1, *Xa2, *Xb2, *Wt, *Wh, *convout;
    float *hb;
    cudaGetSymbolAddress((void**)&Xin, g_Xin);
    cudaGetSymbolAddress((void**)&Xa1, g_Xa1);
    cudaGetSymbolAddress((void**)&Xb1, g_Xb1);
    cudaGetSymbolAddress((void**)&Xa2, g_Xa2);
    cudaGetSymbolAddress((void**)&Xb2, g_Xb2);
    cudaGetSymbolAddress((void**)&Wt, g_Wt);
    cudaGetSymbolAddress((void**)&Wh, g_Wh);
    cudaGetSymbolAddress((void**)&convout, g_convout);
    cudaGetSymbolAddress((void**)&hb, g_hb);

    const long locs_base = (long)BATCH * OUTBOFF;

    prep_weights_kernel<<<(int)((8L * 256 * KDIM + 255) / 256), 256>>>(cls_w, box_w);
    prep_heads_kernel<<<(int)((2L * 128 * KDIM + 255) / 256), 256>>>(
        logits_w, logits_b, ctr_w, ctr_b, reg_w, reg_b);

    const long prep_tot = 5188352L + 5 * BOR_TOTAL;   // 6,468,352
    prep_act_kernel<<<(int)((prep_tot + 255) / 256), 256>>>(
        feats[0], feats[1], feats[2], feats[3], feats[4]);

    __half* srcC[4] = {Xin, Xa1, Xb1, Xa1};
    __half* dstC[4] = {Xa1, Xb1, Xa1, Xb1};
    __half* srcB[4] = {Xin, Xa2, Xb2, Xa2};
    __half* dstB[4] = {Xa2, Xb2, Xa2, Xb2};

    dim3 gconv(1269, 4);
    dim3 ghead(1269, 2);
    const int ag = (int)((10376704L + 255) / 256);

    for (int i = 0; i < 4; i++) {
        conv_mma_kernel<<<gconv, 256, DYN_SMEM>>>(
            Wt + (long)i * 256 * KDIM, 4L * 256 * KDIM,
            cls_b + i * 256, box_b + i * 256,
            srcC[i], srcB[i], convout, nullptr, scales, 0);
        gn_stats2_kernel<<<2560, 256>>>();
        gn_apply_kernel<<<ag, 256>>>(dstC[i], dstB[i],
                                     cls_gn_g + i * 256, cls_gn_b + i * 256,
                                     box_gn_g + i * 256, box_gn_b + i * 256);
    }
    conv_mma_kernel<<<ghead, 256, DYN_SMEM>>>(
        Wh, 128L * KDIM, hb, hb + 128,
        Xb1, Xb2, nullptr, out, scales, 3);

    loc_all_kernel<<<(20267 + 255) / 256, 256>>>(out, locs_base);
}

// round 17
// speedup vs baseline: 2.7538x; 1.1350x over previous
#include <cuda_runtime.h>
#include <cuda_fp16.h>
#include <math.h>
#include <stdint.h>

// ===========================================================================
// FCOS head via mma.sync fp16 tensor cores (compute_100-safe; no tcgen05).
// Conv3x3 as implicit GEMM, plain fp16 W and X. R17 (= audited R16): compact
// 64B-row tiles with chunk-XOR swizzle (conflict-free ldmatrix) -> ring-3
// pipeline with TWO load-stages in flight at 2 CTAs/SM. All 5 FPN levels
// fused per launch; towers fused (grid y=4); fp16 convout; fused GN.
// ===========================================================================

#define BATCH 8
#define KDIM 2304
#define PSMAX 950
#define TOTPAD 170136L
#define TOTPOS 162136L
#define CONVOFF (TOTPOS * 256)
#define OUTBOFF 1722695L

__device__ __constant__ int  c_H[5]    = {100, 50, 25, 13, 7};
__device__ __constant__ int  c_W[5]    = {152, 76, 38, 19, 10};
__device__ __constant__ int  c_HW[5]   = {15200, 3800, 950, 247, 70};
__device__ __constant__ int  c_N[5]    = {121600, 30400, 7600, 1976, 560};
__device__ __constant__ int  c_NBLK[5] = {950, 238, 60, 16, 5};
__device__ __constant__ int  c_BCUM[5] = {950, 1188, 1248, 1264, 1269};
__device__ __constant__ long c_XB[5]   = {0, 125664, 158112, 166752, 169272};
__device__ __constant__ long c_CB[5]   = {0, 121600, 152000, 159600, 161576};
__device__ __constant__ long c_LOFF[5] = {0, 1292000, 1615000, 1695750, 1716745};

// ---------------- device buffers -------------------------------------------
__device__ __align__(16) __half g_Xin[TOTPAD * 256];
__device__ __align__(16) __half g_Xa1[TOTPAD * 256];
__device__ __align__(16) __half g_Xb1[TOTPAD * 256];
__device__ __align__(16) __half g_Xa2[TOTPAD * 256];
__device__ __align__(16) __half g_Xb2[TOTPAD * 256];
__device__ __align__(16) __half g_convout[2 * CONVOFF];
__device__ __align__(16) __half g_Wt[8 * 256 * KDIM];
__device__ __align__(16) __half g_Wh[2 * 128 * KDIM];
__device__ float g_hb[2 * 128];
__device__ float g_psA [2560L * PSMAX];
__device__ float g_ps2A[2560L * PSMAX];
__device__ float g_mean[2560];
__device__ float g_rstd[2560];

// ---------------- PTX helpers ----------------------------------------------
__device__ __forceinline__ uint32_t smem_to_u32(const void* p) {
    uint32_t a;
    asm("{ .reg .u64 t; cvta.to.shared.u64 t, %1; cvt.u32.u64 %0, t; }"
        : "=r"(a) : "l"(p));
    return a;
}
#define CP_ASYNC16(dst, src) \
    asm volatile("cp.async.cg.shared.global [%0], [%1], 16;" \
                 :: "r"(dst), "l"(src))
#define CP_COMMIT() asm volatile("cp.async.commit_group;" ::: "memory")
#define CP_WAIT0()  asm volatile("cp.async.wait_group 0;" ::: "memory")
#define CP_WAIT1()  asm volatile("cp.async.wait_group 1;" ::: "memory")

__device__ __forceinline__ void ldsm4(uint32_t (&r)[4], uint32_t a) {
    asm volatile("ldmatrix.sync.aligned.m8n8.x4.shared.b16 {%0,%1,%2,%3}, [%4];"
        : "=r"(r[0]), "=r"(r[1]), "=r"(r[2]), "=r"(r[3]) : "r"(a));
}
__device__ __forceinline__ void mma16816(float* d, const uint32_t* a, const uint32_t* b) {
    asm volatile(
        "mma.sync.aligned.m16n8k16.row.col.f32.f16.f16.f32 "
        "{%0,%1,%2,%3}, {%4,%5,%6,%7}, {%8,%9}, {%0,%1,%2,%3};"
        : "+f"(d[0]), "+f"(d[1]), "+f"(d[2]), "+f"(d[3])
        : "r"(a[0]), "r"(a[1]), "r"(a[2]), "r"(a[3]), "r"(b[0]), "r"(b[1]));
}

__device__ __forceinline__ int lvl_of_block(int bx) {
    return (bx < c_BCUM[0]) ? 0 : (bx < c_BCUM[1]) ? 1
         : (bx < c_BCUM[2]) ? 2 : (bx < c_BCUM[3]) ? 3 : 4;
}
// Swizzled offset of 16B chunk ch in a 128x64B tile row.
__device__ __forceinline__ uint32_t swz(int row, int ch) {
    return (uint32_t)(row * 64 + ((ch ^ ((row >> 1) & 3)) * 16));
}

// ---------------- prep kernels ---------------------------------------------
__global__ void prep_weights_kernel(const float* __restrict__ cls_w,
                                    const float* __restrict__ box_w)
{
    long idx = (long)blockIdx.x * blockDim.x + threadIdx.x;
    if (idx >= 8L * 256 * KDIM) return;
    int j = (int)(idx / (256 * KDIM));
    int rem = (int)(idx - (long)j * 256 * KDIM);
    int m = rem / KDIM, k = rem - m * KDIM;
    int tap = k >> 8, ci = k & 255;
    const float* src = (j < 4) ? cls_w + (long)j * 256 * KDIM
                               : box_w + (long)(j - 4) * 256 * KDIM;
    g_Wt[idx] = __float2half(src[(m * 256 + ci) * 9 + tap]);
}

__global__ void prep_heads_kernel(const float* __restrict__ logits_w,
                                  const float* __restrict__ logits_b,
                                  const float* __restrict__ ctr_w,
                                  const float* __restrict__ ctr_b,
                                  const float* __restrict__ reg_w,
                                  const float* __restrict__ reg_b)
{
    long idx = (long)blockIdx.x * blockDim.x + threadIdx.x;
    if (idx >= 2L * 128 * KDIM) return;
    int which = (int)(idx / (128 * KDIM));
    int rem = (int)(idx - (long)which * 128 * KDIM);
    int m = rem / KDIM, k = rem - m * KDIM;
    int tap = k >> 8, ci = k & 255;
    float v = 0.f;
    if (which == 0) {
        if (m < 80)       v = logits_w[(m * 256 + ci) * 9 + tap];
        else if (m == 80) v = ctr_w[ci * 9 + tap];
    } else {
        if (m < 4) v = reg_w[(m * 256 + ci) * 9 + tap];
    }
    g_Wh[idx] = __float2half(v);
    if (k == 0) {
        float bv = 0.f;
        if (which == 0) { if (m < 80) bv = logits_b[m]; else if (m == 80) bv = ctr_b[0]; }
        else            { if (m < 4)  bv = reg_b[m]; }
        g_hb[which * 128 + m] = bv;
    }
}

__device__ __constant__ long c_ICUM[5] = {3891200, 4864000, 5107200, 5170432, 5188352};
__device__ __constant__ int  c_LBOR[5] = {130048, 195584, 228864, 246272, 256000};
#define BOR_TOTAL 256000L

__global__ void prep_act_kernel(const float* __restrict__ f0,
                                const float* __restrict__ f1,
                                const float* __restrict__ f2,
                                const float* __restrict__ f3,
                                const float* __restrict__ f4)
{
    long idx = (long)blockIdx.x * blockDim.x + threadIdx.x;
    if (idx < c_ICUM[4]) {
        int l = (idx < c_ICUM[0]) ? 0 : (idx < c_ICUM[1]) ? 1
              : (idx < c_ICUM[2]) ? 2 : (idx < c_ICUM[3]) ? 3 : 4;
        long r = idx - (l ? c_ICUM[l - 1] : 0);
        const int HW = c_HW[l], W = c_W[l], Wp = W + 2, Hp = c_H[l] + 2;
        const int NP = c_N[l];
        int g = (int)(r / NP);
        int p = (int)(r - (long)g * NP);
        int b = p / HW, hw = p - b * HW;
        int y = hw / W, x = hw - y * W;
        const float* feat = (l == 0) ? f0 : (l == 1) ? f1 : (l == 2) ? f2
                          : (l == 3) ? f3 : f4;
        const float* src = feat + ((long)b * 256 + g * 8) * HW + hw;
        __half hh[8];
#pragma unroll
        for (int i = 0; i < 8; i++) hh[i] = __float2half(src[(long)i * HW]);
        long a = (c_XB[l] + (long)(b * Hp + y + 1) * Wp + x + 1) * 256 + g * 8;
        *(uint4*)(g_Xin + a) = *(const uint4*)hh;
        return;
    }
    idx -= c_ICUM[4];
    if (idx >= 5 * BOR_TOTAL) return;
    int buf = (int)(idx / BOR_TOTAL);
    int rb = (int)(idx - (long)buf * BOR_TOTAL);
    int l = (rb < c_LBOR[0]) ? 0 : (rb < c_LBOR[1]) ? 1
          : (rb < c_LBOR[2]) ? 2 : (rb < c_LBOR[3]) ? 3 : 4;
    int r0 = rb - (l ? c_LBOR[l - 1] : 0);
    const int H = c_H[l], W = c_W[l], Hp = H + 2, Wp = W + 2;
    const int cnt = 2 * Wp + 2 * H;
    int b = r0 / (cnt * 32);
    int r = r0 - b * cnt * 32;
    int i = r >> 5, q = r & 31;
    int y, x;
    if (i < Wp)              { y = 0;      x = i; }
    else if (i < 2 * Wp)     { y = Hp - 1; x = i - Wp; }
    else if (i < 2 * Wp + H) { y = 1 + (i - 2 * Wp);     x = 0; }
    else                     { y = 1 + (i - 2 * Wp - H); x = Wp - 1; }
    long a = (c_XB[l] + (long)(b * Hp + y) * Wp + x) * 256 + q * 8;
    __half* dst = (buf == 0) ? g_Xin : (buf == 1) ? g_Xa1 : (buf == 2) ? g_Xb1
                 : (buf == 3) ? g_Xa2 : g_Xb2;
    *(uint4*)(dst + a) = make_uint4(0, 0, 0, 0);
}

// ---------------- conv via mma.sync (all levels fused, ring-3) --------------
#define TILE_BYTES 8192                  // 128 rows x 64B, swizzled
#define STAGE_B (4 * TILE_BYTES)         // 32768
#define RING 3
#define DYN_SMEM (RING * STAGE_B + 512 + 64)

__global__ __launch_bounds__(256, 2) void conv_mma_kernel(
    const __half* __restrict__ Wt, long wstride,
    const float* __restrict__ bias, const float* __restrict__ bias2,
    const __half* __restrict__ Xp, const __half* __restrict__ Xp2,
    __half* __restrict__ convout, float* __restrict__ dout,
    const float* __restrict__ scales, int mode)
{
    const int bx = blockIdx.x;
    const int l = lvl_of_block(bx);
    const int lb = bx - (l ? c_BCUM[l - 1] : 0);
    const int H = c_H[l], W = c_W[l], HW = c_HW[l], N = c_N[l];
    const int Hp = H + 2, Wp = W + 2;
    const int n0 = lb * 128;
    const int by = blockIdx.y;
    int tower, m0, emode, Meff;
    if (mode == 0) { tower = by >> 1; m0 = (by & 1) * 128; emode = 0; Meff = 128; }
    else           { tower = by; m0 = 0; emode = tower ? 2 : 1; Meff = tower ? 4 : 85; }
    const __half* Wb = Wt + (long)tower * wstride;
    const __half* Xs = (tower ? Xp2 : Xp) + c_XB[l] * 256;
    const float* biasP = tower ? bias2 : bias;

    const int tid = threadIdx.x, wid = tid >> 5, lid = tid & 31;

    extern __shared__ char dsm[];
    const uint32_t sb0 = smem_to_u32(dsm);
    int* sbase = (int*)(dsm + RING * STAGE_B);

    if (tid < 128) {
        int p = n0 + tid;
        if (p >= N) p = N - 1;
        int b = p / HW, hw = p - b * HW;
        int y = hw / W, x = hw - y * W;
        sbase[tid] = ((b * Hp + y) * Wp + x) * 256;
    }
    __syncthreads();

    // 8 cp.async channels (16B each) per stage, swizzled destinations.
    const __half* gbase[8];
    uint32_t sdst[8];
    bool isA[8];
    int ksub[8];
#pragma unroll
    for (int c = 0; c < 8; c++) {
        int id = c * 256 + tid;
        int tile = id >> 9;            // 0:W_e 1:W_o 2:X_e 3:X_o
        int e = id & 511;
        int row = e >> 2, c4 = e & 3;
        isA[c] = (tile < 2);
        ksub[c] = tile & 1;
        if (tile < 2) gbase[c] = Wb + (long)(m0 + row) * KDIM + c4 * 8;
        else          gbase[c] = Xs + (long)sbase[row] + c4 * 8;
        sdst[c] = sb0 + tile * TILE_BYTES + swz(row, c4);
    }

    const int NST = KDIM / 64;         // 36
    const int wm = wid & 3, wn = wid >> 2;
    const bool um0 = (wm * 32) < Meff;
    const bool um1 = (wm * 32 + 16) < Meff;

    float acc[2][8][4];
#pragma unroll
    for (int i = 0; i < 2; i++)
#pragma unroll
        for (int j = 0; j < 8; j++)
#pragma unroll
            for (int k = 0; k < 4; k++) acc[i][j][k] = 0.f;

    auto issue = [&](int ss) {
        const uint32_t boff = (uint32_t)(ss % RING) * STAGE_B;
#pragma unroll
        for (int c = 0; c < 8; c++) {
            const int kc = 2 * ss + ksub[c];
            long off;
            if (isA[c]) off = kc * 32;
            else {
                const int tap = kc >> 3;
                off = ((tap / 3) * Wp + (tap % 3)) * 256 + (kc & 7) * 32;
            }
            CP_ASYNC16(sdst[c] + boff, gbase[c] + off);
        }
        CP_COMMIT();
    };

    issue(0); issue(1);
    for (int ss = 0; ss < NST; ss++) {
        if (ss + 1 < NST) { CP_WAIT1(); } else { CP_WAIT0(); }
        __syncthreads();
        if (ss + 2 < NST) issue(ss + 2);   // slot (ss+2)%3 consumed in iter ss-1

        const uint32_t tb = sb0 + (uint32_t)(ss % RING) * STAGE_B;
#pragma unroll
        for (int sub = 0; sub < 2; sub++) {
            const uint32_t Ab = tb + sub * TILE_BYTES;
            const uint32_t Bb = tb + (2 + sub) * TILE_BYTES;
#pragma unroll
            for (int sl = 0; sl < 2; sl++) {
                uint32_t ah[2][4];
                const int ach = sl * 2 + (lid >> 4);
                if (um0) {
                    const int ar = wm * 32 + (lid & 15);
                    ldsm4(ah[0], Ab + swz(ar, ach));
                }
                if (um1) {
                    const int ar = wm * 32 + 16 + (lid & 15);
                    ldsm4(ah[1], Ab + swz(ar, ach));
                }
#pragma unroll
                for (int ng = 0; ng < 4; ng++) {
                    const int q = lid >> 3;
                    const int br = wn * 64 + ng * 16 + (q >> 1) * 8 + (lid & 7);
                    const int bch = sl * 2 + (q & 1);
                    uint32_t bh[4];
                    ldsm4(bh, Bb + swz(br, bch));
                    if (um0) {
#pragma unroll
                        for (int h = 0; h < 2; h++)
                            mma16816(acc[0][ng * 2 + h], ah[0], &bh[h * 2]);
                    }
                    if (um1) {
#pragma unroll
                        for (int h = 0; h < 2; h++)
                            mma16816(acc[1][ng * 2 + h], ah[1], &bh[h * 2]);
                    }
                }
            }
        }
    }
    __syncthreads();

    // ---------------- epilogue ----------------
    const float sc = (emode == 2) ? scales[l] : 0.f;
    const int b0 = n0 / HW;
    float* sred = (float*)dsm;
    float ts[12], ts2[12];
    if (emode == 0) {
        if (tid < 96) sred[tid] = 0.f;
#pragma unroll
        for (int i = 0; i < 12; i++) { ts[i] = 0.f; ts2[i] = 0.f; }
        __syncthreads();
    }
    __half* cvo = convout + (size_t)tower * CONVOFF;

#pragma unroll
    for (int mi = 0; mi < 2; mi++) {
        if (!(mi == 0 ? um0 : um1)) continue;
        const int mlo = m0 + wm * 32 + mi * 16 + (lid >> 2);
        const float bv0 = biasP[mlo];
        const float bv1 = biasP[mlo + 8];
#pragma unroll
        for (int ng = 0; ng < 4; ng++) {
#pragma unroll
            for (int h = 0; h < 2; h++) {
                const float* d = acc[mi][ng * 2 + h];
                const int n = n0 + wn * 64 + ng * 16 + h * 8 + 2 * (lid & 3);
#pragma unroll
                for (int e = 0; e < 4; e++) {
                    const int p = n + (e & 1);
                    const int half_ = (e >> 1);
                    const int m = mlo + half_ * 8;
                    if (p >= N) continue;
                    float v = d[e] + (half_ ? bv1 : bv0);
                    if (emode == 0) {
                        cvo[(c_CB[l] + p) * 256 + m] = __float2half(v);
                        int db = p / HW - b0;
                        int si = (mi * 2 + half_) * 3 + db;
                        ts[si] += v; ts2[si] += v * v;
                    } else {
                        int b = p / HW, hw = p - b * HW;
                        long ob = (long)b * OUTBOFF + c_LOFF[l];
                        if (emode == 1) {
                            if (m < 80)       dout[ob + (long)m * HW + hw] = v;
                            else if (m == 80) dout[ob + 84L * HW + hw] = v;
                        } else {
                            if (m < 4) dout[ob + (long)(80 + m) * HW + hw] = expf(sc * v);
                        }
                    }
                }
            }
        }
    }

    if (emode == 0) {
#pragma unroll
        for (int i = 0; i < 12; i++) {
            if (ts[i] == 0.f && ts2[i] == 0.f) continue;
            int db = i % 3, q = i / 3;
            int half_ = q & 1, mi = q >> 1;
            int gl = wm * 4 + mi * 2 + half_;
            atomicAdd(&sred[db * 16 + gl], ts[i]);
            atomicAdd(&sred[48 + db * 16 + gl], ts2[i]);
        }
        __syncthreads();
        if (tid < 48) {
            int db = tid >> 4, gl = tid & 15;
            int b = b0 + db;
            if (b < BATCH) {
                int g = (m0 >> 3) + gl;
                long bg = (long)(l * 2 + tower) * 256 + b * 32 + g;
                g_psA [bg * PSMAX + lb] = sred[tid];
                g_ps2A[bg * PSMAX + lb] = sred[48 + tid];
            }
        }
    }
}

// ---------------- GroupNorm stage 2 (all levels) -----------------------------
__global__ __launch_bounds__(256) void gn_stats2_kernel()
{
    const int bg = blockIdx.x;
    const int l = bg >> 9;
    const int b = (bg >> 5) & 7;
    const int HW = c_HW[l], N = c_N[l], nblk = c_NBLK[l];
    float s = 0.f, s2 = 0.f;
    for (int nb = threadIdx.x; nb < nblk; nb += 256) {
        int p0 = nb * 128;
        int bfirst = p0 / HW;
        int pl = p0 + 127; if (pl >= N) pl = N - 1;
        int blast = pl / HW;
        if (b >= bfirst && b <= blast) {
            s  += g_psA [(long)bg * PSMAX + nb];
            s2 += g_ps2A[(long)bg * PSMAX + nb];
        }
    }
    __shared__ float ss[256], ss2[256];
    ss[threadIdx.x] = s; ss2[threadIdx.x] = s2;
    __syncthreads();
    for (int o = 128; o > 0; o >>= 1) {
        if (threadIdx.x < o) {
            ss[threadIdx.x]  += ss[threadIdx.x + o];
            ss2[threadIdx.x] += ss2[threadIdx.x + o];
        }
        __syncthreads();
    }
    if (threadIdx.x == 0) {
        float cnt = 8.f * HW;
        float mean = ss[0] / cnt;
        float var  = ss2[0] / cnt - mean * mean;
        g_mean[bg] = mean;
        g_rstd[bg] = rsqrtf(var + 1e-5f);
    }
}

// GN apply + ReLU, all levels + both towers fused.
__device__ __constant__ long c_A2CUM[5] =
    {7782400, 9728000, 10214400, 10340864, 10376704};

__global__ __launch_bounds__(256) void gn_apply_kernel(
    __half* __restrict__ dstC, __half* __restrict__ dstB,
    const float* __restrict__ gammaC, const float* __restrict__ betaC,
    const float* __restrict__ gammaB, const float* __restrict__ betaB)
{
    long idx = (long)blockIdx.x * blockDim.x + threadIdx.x;
    if (idx >= c_A2CUM[4]) return;
    int l = (idx < c_A2CUM[0]) ? 0 : (idx < c_A2CUM[1]) ? 1
          : (idx < c_A2CUM[2]) ? 2 : (idx < c_A2CUM[3]) ? 3 : 4;
    long r = idx - (l ? c_A2CUM[l - 1] : 0);
    const int HW = c_HW[l], W = c_W[l], Hp = c_H[l] + 2, Wp = W + 2;
    const long NT = (long)c_N[l] * 32;
    const int tower = (r >= NT);
    if (tower) r -= NT;
    int g = (int)(r & 31);
    int p = (int)(r >> 5);
    int b = p / HW, hw = p - b * HW;
    int y = hw / W, x = hw - y * W;
    const int bg = (l * 2 + tower) * 256 + b * 32 + g;
    const float mean = g_mean[bg], rstd = g_rstd[bg];
    const float* gamma = tower ? gammaB : gammaC;
    const float* beta  = tower ? betaB  : betaC;
    const __half* src = g_convout + (size_t)tower * CONVOFF
                        + (c_CB[l] + p) * 256 + g * 8;
    uint4 raw = __ldcs((const uint4*)src);
    const __half* hv = (const __half*)&raw;
    __half hh[8];
#pragma unroll
    for (int i = 0; i < 8; i++) {
        int c = g * 8 + i;
        float v = (__half2float(hv[i]) - mean) * rstd * gamma[c] + beta[c];
        hh[i] = __float2half(v > 0.f ? v : 0.f);
    }
    long a = (c_XB[l] + (long)(b * Hp + y + 1) * Wp + x + 1) * 256 + g * 8;
    __half* dst = tower ? dstB : dstC;
    *(uint4*)(dst + a) = *(const uint4*)hh;
}

// All-level FCOS locations.
__global__ __launch_bounds__(256) void loc_all_kernel(float* __restrict__ out, long base)
{
    static const int WS_[5] = {152, 76, 38, 19, 10};
    static const int STR[5] = {8, 16, 32, 64, 128};
    static const int OFF[5] = {0, 15200, 19000, 19950, 20197};
    int idx = blockIdx.x * blockDim.x + threadIdx.x;
    if (idx >= 20267) return;
    int l = 4;
    if (idx < 15200) l = 0;
    else if (idx < 19000) l = 1;
    else if (idx < 19950) l = 2;
    else if (idx < 20197) l = 3;
    int r = idx - OFF[l];
    int y = r / WS_[l], x = r - y * WS_[l];
    out[base + 2 * idx]     = (float)(x * STR[l] + STR[l] / 2);
    out[base + 2 * idx + 1] = (float)(y * STR[l] + STR[l] / 2);
}

// ---------------------------------------------------------------------------
extern "C" void kernel_launch(void* const* d_in, const int* in_sizes, int n_in,
                              void* d_out, int out_size)
{
    (void)in_sizes; (void)n_in; (void)out_size;
    const float* feats[5];
    for (int i = 0; i < 5; i++) feats[i] = (const float*)d_in[i];
    const float* cls_w    = (const float*)d_in[5];
    const float* cls_b    = (const float*)d_in[6];
    const float* cls_gn_g = (const float*)d_in[7];
    const float* cls_gn_b = (const float*)d_in[8];
    const float* box_w    = (const float*)d_in[9];
    const float* box_b    = (const float*)d_in[10];
    const float* box_gn_g = (const float*)d_in[11];
    const float* box_gn_b = (const float*)d_in[12];
    const float* logits_w = (const float*)d_in[13];
    const float* logits_b = (const float*)d_in[14];
    const float* ctr_w    = (const float*)d_in[15];
    const float* ctr_b    = (const float*)d_in[16];
    const float* reg_w    = (const float*)d_in[17];
    const float* reg_b    = (const float*)d_in[18];
    const float* scales   = (const float*)d_in[19];
    float* out = (float*)d_out;

    cudaFuncSetAttribute(conv_mma_kernel,
                         cudaFuncAttributeMaxDynamicSharedMemorySize, DYN_SMEM);

    __half *Xin, *Xa1, *Xb1, *Xa2, *Xb2, *Wt, *Wh, *convout;
    float *hb;
    cudaGetSymbolAddress((void**)&Xin, g_Xin);
    cudaGetSymbolAddress((void**)&Xa1, g_Xa1);
    cudaGetSymbolAddress((void**)&Xb1, g_Xb1);
    cudaGetSymbolAddress((void**)&Xa2, g_Xa2);
    cudaGetSymbolAddress((void**)&Xb2, g_Xb2);
    cudaGetSymbolAddress((void**)&Wt, g_Wt);
    cudaGetSymbolAddress((void**)&Wh, g_Wh);
    cudaGetSymbolAddress((void**)&convout, g_convout);
    cudaGetSymbolAddress((void**)&hb, g_hb);

    const long locs_base = (long)BATCH * OUTBOFF;

    prep_weights_kernel<<<(int)((8L * 256 * KDIM + 255) / 256), 256>>>(cls_w, box_w);
    prep_heads_kernel<<<(int)((2L * 128 * KDIM + 255) / 256), 256>>>(
        logits_w, logits_b, ctr_w, ctr_b, reg_w, reg_b);

    const long prep_tot = 5188352L + 5 * BOR_TOTAL;
    prep_act_kernel<<<(int)((prep_tot + 255) / 256), 256>>>(
        feats[0], feats[1], feats[2], feats[3], feats[4]);

    __half* srcC[4] = {Xin, Xa1, Xb1, Xa1};
    __half* dstC[4] = {Xa1, Xb1, Xa1, Xb1};
    __half* srcB[4] = {Xin, Xa2, Xb2, Xa2};
    __half* dstB[4] = {Xa2, Xb2, Xa2, Xb2};

    dim3 gconv(1269, 4);
    dim3 ghead(1269, 2);
    const int ag = (int)((10376704L + 255) / 256);

    for (int i = 0; i < 4; i++) {
        conv_mma_kernel<<<gconv, 256, DYN_SMEM>>>(
            Wt + (long)i * 256 * KDIM, 4L * 256 * KDIM,
            cls_b + i * 256, box_b + i * 256,
            srcC[i], srcB[i], convout, nullptr, scales, 0);
        gn_stats2_kernel<<<2560, 256>>>();
        gn_apply_kernel<<<ag, 256>>>(dstC[i], dstB[i],
                                     cls_gn_g + i * 256, cls_gn_b + i * 256,
                                     box_gn_g + i * 256, box_gn_b + i * 256);
    }
    conv_mma_kernel<<<ghead, 256, DYN_SMEM>>>(
        Wh, 128L * KDIM, hb, hb + 128,
        Xb1, Xb2, nullptr, out, scales, 3);

    loc_all_kernel<<<(20267 + 255) / 256, 256>>>(out, locs_base);
}